// round 13
// baseline (speedup 1.0000x reference)
#include <cuda_runtime.h>
#include <cuda_bf16.h>
#include <math.h>

#define BD   2
#define SD   1024
#define DD   1024
#define HH   16
#define HDIM 64
#define LL   4
#define MMF  2730
#define MP   2752
#define VV   32000
#define NTOK (BD*SD)
#define BH   (BD*HH)

// ---------------- scratch (device globals; no allocation allowed) ----------
__device__ float g_x[NTOK*DD];
__device__ float g_gate[(long)NTOK*MP];     // also reused as split-K partial p0
__device__ float g_up[(long)NTOK*MP];       // also reused as split-K partial p1

__device__ __nv_bfloat16 g_h_h[NTOK*DD],    g_h_l[NTOK*DD];
__device__ __nv_bfloat16 g_attn_h[NTOK*DD], g_attn_l[NTOK*DD];
__device__ __nv_bfloat16 g_gate_h[NTOK*MP], g_gate_l[NTOK*MP];

__device__ __nv_bfloat16 g_q_h[BH*SD*HDIM], g_q_l[BH*SD*HDIM];
__device__ __nv_bfloat16 g_k_h[BH*SD*HDIM], g_k_l[BH*SD*HDIM];
__device__ __nv_bfloat16 g_v_h[BH*SD*HDIM], g_v_l[BH*SD*HDIM];

__device__ __nv_bfloat16 g_wqkvT_h[LL*3*DD*DD], g_wqkvT_l[LL*3*DD*DD];
__device__ __nv_bfloat16 g_woutT_h[LL*DD*DD],   g_woutT_l[LL*DD*DD];
__device__ __nv_bfloat16 g_wgT_h[LL*MMF*DD],    g_wgT_l[LL*MMF*DD];
__device__ __nv_bfloat16 g_wuT_h[LL*MMF*DD],    g_wuT_l[LL*MMF*DD];
__device__ __nv_bfloat16 g_wdT_h[(long)LL*DD*MP], g_wdT_l[(long)LL*DD*MP];

// ---------------- helpers ----------------------------------------------------
__device__ __forceinline__ void split_bf(float f, __nv_bfloat16& h, __nv_bfloat16& l) {
    h = __float2bfloat16(f);
    l = __float2bfloat16(f - __bfloat162float(h));
}
__device__ __forceinline__ void pack_split2(float a, float b, unsigned& hi, unsigned& lo) {
    __nv_bfloat162 th, tl;
    th.x = __float2bfloat16(a);
    th.y = __float2bfloat16(b);
    tl.x = __float2bfloat16(a - __bfloat162float(th.x));
    tl.y = __float2bfloat16(b - __bfloat162float(th.y));
    hi = *(unsigned*)&th;
    lo = *(unsigned*)&tl;
}
__device__ __forceinline__ void mma_bf16(float* d, const unsigned* a,
                                         const unsigned* b, const float* c) {
    asm volatile(
        "mma.sync.aligned.m16n8k16.row.col.f32.bf16.bf16.f32 "
        "{%0,%1,%2,%3}, {%4,%5,%6,%7}, {%8,%9}, {%10,%11,%12,%13};"
        : "=f"(d[0]), "=f"(d[1]), "=f"(d[2]), "=f"(d[3])
        : "r"(a[0]), "r"(a[1]), "r"(a[2]), "r"(a[3]),
          "r"(b[0]), "r"(b[1]),
          "f"(c[0]), "f"(c[1]), "f"(c[2]), "f"(c[3]));
}
__device__ __forceinline__ void ldsm4(unsigned& r0, unsigned& r1, unsigned& r2,
                                      unsigned& r3, unsigned addr) {
    asm volatile("ldmatrix.sync.aligned.m8n8.x4.shared.b16 {%0,%1,%2,%3}, [%4];"
                 : "=r"(r0), "=r"(r1), "=r"(r2), "=r"(r3) : "r"(addr));
}
__device__ __forceinline__ void ldsm4t(unsigned& r0, unsigned& r1, unsigned& r2,
                                       unsigned& r3, unsigned addr) {
    asm volatile("ldmatrix.sync.aligned.m8n8.x4.trans.shared.b16 {%0,%1,%2,%3}, [%4];"
                 : "=r"(r0), "=r"(r1), "=r"(r2), "=r"(r3) : "r"(addr));
}
__device__ __forceinline__ void cp16(unsigned saddr, const void* g) {
    asm volatile("cp.async.cg.shared.global [%0], [%1], 16;" :: "r"(saddr), "l"(g));
}
__device__ __forceinline__ void cp_commit() {
    asm volatile("cp.async.commit_group;");
}
template<int N> __device__ __forceinline__ void cp_wait() {
    asm volatile("cp.async.wait_group %0;" :: "n"(N));
}

// ---------------- weight transpose + bf16 split ------------------------------
__global__ void k_wsplit(const float* __restrict__ W,
                         __nv_bfloat16* __restrict__ Th,
                         __nv_bfloat16* __restrict__ Tl,
                         int K, int M, int KP, long wstride, long tstride) {
    W  += (long)blockIdx.z * wstride;
    Th += (long)blockIdx.z * tstride;
    Tl += (long)blockIdx.z * tstride;
    __shared__ float t[64][33];
    int m0 = blockIdx.x * 32, k0 = blockIdx.y * 64;
    int tx = threadIdx.x, ty = threadIdx.y;
    #pragma unroll
    for (int i = 0; i < 64; i += 8) {
        int k = k0 + ty + i, m = m0 + tx;
        t[ty + i][tx] = (k < K && m < M) ? W[(long)k * M + m] : 0.f;
    }
    __syncthreads();
    #pragma unroll
    for (int i = 0; i < 32; i += 8) {
        int m = m0 + ty + i, kk = k0 + tx * 2;
        if (m < M && kk < KP) {
            __nv_bfloat16 h0, l0, h1, l1;
            split_bf(t[tx * 2][ty + i], h0, l0);
            split_bf(t[tx * 2 + 1][ty + i], h1, l1);
            __nv_bfloat162 ph; ph.x = h0; ph.y = h1;
            __nv_bfloat162 pl; pl.x = l0; pl.y = l1;
            ((unsigned*)Th)[((long)m * KP + kk) >> 1] = *(unsigned*)&ph;
            ((unsigned*)Tl)[((long)m * KP + kk) >> 1] = *(unsigned*)&pl;
        }
    }
}

__global__ void k_embed(const int* __restrict__ tok, const float* __restrict__ emb,
                        float* __restrict__ x) {
    int i = blockIdx.x * 256 + threadIdx.x;
    int n = i >> 8, c4 = (i & 255) * 4;
    *(float4*)(x + (long)n * DD + c4) =
        *(const float4*)(emb + (long)tok[n] * DD + c4);
}

__global__ void __launch_bounds__(256) k_rmsnorm(const float* __restrict__ x,
                                                 const float* __restrict__ w,
                                                 __nv_bfloat16* __restrict__ oh,
                                                 __nv_bfloat16* __restrict__ ol) {
    int row = blockIdx.x;
    int c4 = threadIdx.x * 4;
    float4 xv = *(const float4*)(x + (long)row * DD + c4);
    float s = xv.x * xv.x + xv.y * xv.y + xv.z * xv.z + xv.w * xv.w;
    __shared__ float red[8];
    #pragma unroll
    for (int off = 16; off; off >>= 1) s += __shfl_xor_sync(0xffffffffu, s, off);
    if ((threadIdx.x & 31) == 0) red[threadIdx.x >> 5] = s;
    __syncthreads();
    if (threadIdx.x == 0) {
        float tt = 0.f;
        #pragma unroll
        for (int i = 0; i < 8; ++i) tt += red[i];
        red[0] = tt;
    }
    __syncthreads();
    float r = rsqrtf(red[0] * (1.0f / DD) + 1e-6f);
    float4 wv = *(const float4*)(w + c4);
    unsigned h0, l0, h1, l1;
    pack_split2(xv.x * r * wv.x, xv.y * r * wv.y, h0, l0);
    pack_split2(xv.z * r * wv.z, xv.w * r * wv.w, h1, l1);
    long wi = ((long)row * DD + c4) >> 1;
    ((unsigned*)oh)[wi] = h0;
    ((unsigned*)oh)[wi + 1] = h1;
    ((unsigned*)ol)[wi] = l0;
    ((unsigned*)ol)[wi + 1] = l1;
}

// ---- combine split-K partials + residual + bias, then rmsnorm -> bf16 split -
__global__ void __launch_bounds__(256) k_comb_rms(float* __restrict__ x,
                                                  const float* __restrict__ p0,
                                                  const float* __restrict__ p1,
                                                  const float* __restrict__ bias,
                                                  const float* __restrict__ w,
                                                  __nv_bfloat16* __restrict__ oh,
                                                  __nv_bfloat16* __restrict__ ol) {
    int row = blockIdx.x;
    int c4 = threadIdx.x * 4;
    long base = (long)row * DD + c4;
    float4 xv = *(float4*)(x + base);
    float4 a = *(const float4*)(p0 + base);
    float4 b = *(const float4*)(p1 + base);
    float4 bv = *(const float4*)(bias + c4);
    xv.x += a.x + b.x + bv.x;
    xv.y += a.y + b.y + bv.y;
    xv.z += a.z + b.z + bv.z;
    xv.w += a.w + b.w + bv.w;
    *(float4*)(x + base) = xv;
    float s = xv.x * xv.x + xv.y * xv.y + xv.z * xv.z + xv.w * xv.w;
    __shared__ float red[8];
    #pragma unroll
    for (int off = 16; off; off >>= 1) s += __shfl_xor_sync(0xffffffffu, s, off);
    if ((threadIdx.x & 31) == 0) red[threadIdx.x >> 5] = s;
    __syncthreads();
    if (threadIdx.x == 0) {
        float tt = 0.f;
        #pragma unroll
        for (int i = 0; i < 8; ++i) tt += red[i];
        red[0] = tt;
    }
    __syncthreads();
    float r = rsqrtf(red[0] * (1.0f / DD) + 1e-6f);
    float4 wv = *(const float4*)(w + c4);
    unsigned h0, l0, h1, l1;
    pack_split2(xv.x * r * wv.x, xv.y * r * wv.y, h0, l0);
    pack_split2(xv.z * r * wv.z, xv.w * r * wv.w, h1, l1);
    long wi = base >> 1;
    ((unsigned*)oh)[wi] = h0;
    ((unsigned*)oh)[wi + 1] = h1;
    ((unsigned*)ol)[wi] = l0;
    ((unsigned*)ol)[wi + 1] = l1;
}

#define XS 20
// ---------------- 64x128 tile GEMM: persistent + dual + qkv epilogue --------
// smem/stage: A(64x20)+Al + B(128x20)+Bl = 7680 words = 30720 B; 2 stages.
#define A64 (64*XS)
#define B64 (128*XS)
#define STG64 (2*A64 + 2*B64)          // words per stage = 7680
__global__ void __launch_bounds__(256, 2) k_gemm64(
        const __nv_bfloat16* __restrict__ Ah_, const __nv_bfloat16* __restrict__ Al_,
        const __nv_bfloat16* __restrict__ B1h_, const __nv_bfloat16* __restrict__ B1l_,
        const float* __restrict__ bias1, float* __restrict__ C1,
        const __nv_bfloat16* __restrict__ B2h_, const __nv_bfloat16* __restrict__ B2l_,
        const float* __restrict__ bias2, float* __restrict__ C2,
        int N, int K, int M, int tilesX, int ldC, int Mstore, int qkv_mode,
        __nv_bfloat16* qh, __nv_bfloat16* ql,
        __nv_bfloat16* kh, __nv_bfloat16* kl,
        __nv_bfloat16* vh, __nv_bfloat16* vl) {
    extern __shared__ unsigned sm[];
    const unsigned* Ahw = (const unsigned*)Ah_;
    const unsigned* Alw = (const unsigned*)Al_;
    int tid = threadIdx.x, wid = tid >> 5, lane = tid & 31;
    int wm = (wid & 1) * 32, wn = (wid >> 1) * 32;
    int Kw = K >> 1;
    int NC = Kw >> 4;
    unsigned sbase = (unsigned)__cvta_generic_to_shared(sm);
    int tilesY = N >> 6;
    int per = tilesX * tilesY;
    int total = B2h_ ? 2 * per : per;

    int lrow = tid >> 2, lw4 = (tid & 3) * 4;
    int rq   = lane & 7;
    int a_r  = rq + ((lane >> 3) & 1) * 8;
    int a_wo = ((lane >> 4) << 2);
    int b_r  = rq + ((lane >> 4) << 3);
    int b_wo = (((lane >> 3) & 1) << 2);
    int g = lane >> 2, t = lane & 3;

    for (int tI = blockIdx.x; tI < total; tI += gridDim.x) {
        int sel = (tI >= per) ? 1 : 0;
        int tt = sel ? tI - per : tI;
        int by = tt / tilesX, bx = tt - by * tilesX;
        int br = by * 64, bc = bx * 128;
        const unsigned* Bhw = (const unsigned*)(sel ? B2h_ : B1h_);
        const unsigned* Blw = (const unsigned*)(sel ? B2l_ : B1l_);
        const float* bias = sel ? bias2 : bias1;
        float* C = sel ? C2 : C1;

        int brow0 = bc + lrow;      if (brow0 >= M) brow0 = M - 1;
        int brow1 = bc + lrow + 64; if (brow1 >= M) brow1 = M - 1;
        float acc[2][4][4] = {};

        auto load_chunk = [&](int c, int stage) {
            int kw = c * 16 + lw4;
            unsigned sb = sbase + (unsigned)stage * (STG64 * 4u);
            unsigned da = sb + (lrow * XS + lw4) * 4u;
            long a0 = (long)(br + lrow) * Kw + kw;
            cp16(da,            Ahw + a0);
            cp16(da + A64 * 4u, Alw + a0);
            unsigned db = sb + 2u * A64 * 4u + (lrow * XS + lw4) * 4u;
            long b0 = (long)brow0 * Kw + kw;
            long b1 = (long)brow1 * Kw + kw;
            cp16(db,                         Bhw + b0);
            cp16(db + 64u * XS * 4u,         Bhw + b1);
            cp16(db + B64 * 4u,              Blw + b0);
            cp16(db + B64 * 4u + 64u * XS * 4u, Blw + b1);
            cp_commit();
        };

        load_chunk(0, 0);

        for (int c = 0; c < NC; ++c) {
            if (c + 1 < NC) {
                load_chunk(c + 1, (c + 1) & 1);
                cp_wait<1>();
            } else {
                cp_wait<0>();
            }
            __syncthreads();
            unsigned stg = sbase + (unsigned)(c & 1) * (STG64 * 4u);
            unsigned aAh = stg;
            unsigned aAl = stg + A64 * 4u;
            unsigned aBh = stg + 2u * A64 * 4u;
            unsigned aBl = aBh + B64 * 4u;
            #pragma unroll
            for (int ks = 0; ks < 2; ++ks) {
                int kpb = ks * 8;
                unsigned ah[2][4], al[2][4], bh[4][2], bl[4][2];
                #pragma unroll
                for (int mt = 0; mt < 2; ++mt) {
                    unsigned off = (unsigned)(((wm + mt * 16 + a_r) * XS + kpb + a_wo) * 4);
                    ldsm4(ah[mt][0], ah[mt][1], ah[mt][2], ah[mt][3], aAh + off);
                    ldsm4(al[mt][0], al[mt][1], al[mt][2], al[mt][3], aAl + off);
                }
                #pragma unroll
                for (int p = 0; p < 2; ++p) {
                    unsigned off = (unsigned)(((wn + p * 16 + b_r) * XS + kpb + b_wo) * 4);
                    ldsm4(bh[2*p][0], bh[2*p][1], bh[2*p+1][0], bh[2*p+1][1], aBh + off);
                    ldsm4(bl[2*p][0], bl[2*p][1], bl[2*p+1][0], bl[2*p+1][1], aBl + off);
                }
                #pragma unroll
                for (int mt = 0; mt < 2; ++mt)
                    #pragma unroll
                    for (int nt = 0; nt < 4; ++nt) {
                        mma_bf16(acc[mt][nt], ah[mt], bh[nt], acc[mt][nt]);
                        mma_bf16(acc[mt][nt], ah[mt], bl[nt], acc[mt][nt]);
                        mma_bf16(acc[mt][nt], al[mt], bh[nt], acc[mt][nt]);
                    }
            }
            __syncthreads();
        }

        if (qkv_mode) {
            int sec = bc >> 10;
            #pragma unroll
            for (int nt = 0; nt < 4; ++nt) {
                int c0x = bc + wn + nt * 8 + 2 * t;
                int cc = c0x & 1023;
                int h = cc >> 6, j = (cc & 63) >> 1;
                float b0 = bias[c0x], b1 = bias[c0x + 1];
                float freq = exp2f(-0.41524101186f * (float)j);
                __nv_bfloat16* oh = (sec == 0) ? qh : (sec == 1) ? kh : vh;
                __nv_bfloat16* ol = (sec == 0) ? ql : (sec == 1) ? kl : vl;
                #pragma unroll
                for (int mt = 0; mt < 2; ++mt) {
                    #pragma unroll
                    for (int rr = 0; rr < 2; ++rr) {
                        int tok = br + wm + mt * 16 + g + rr * 8;
                        float e = acc[mt][nt][rr * 2 + 0] + b0;
                        float o = acc[mt][nt][rr * 2 + 1] + b1;
                        int s = tok & (SD - 1), b = tok >> 10;
                        if (sec < 2) {
                            float sn, cs;
                            sincosf((float)s * freq, &sn, &cs);
                            float e2 = e * cs - o * sn;
                            o = e * sn + o * cs;
                            e = e2;
                        }
                        long off = ((long)(b * HH + h) * SD + s) * 32 + j;
                        unsigned hi, lo;
                        pack_split2(e, o, hi, lo);
                        ((unsigned*)oh)[off] = hi;
                        ((unsigned*)ol)[off] = lo;
                    }
                }
            }
        } else {
            #pragma unroll
            for (int mt = 0; mt < 2; ++mt) {
                int r0 = br + wm + mt * 16 + g;
                #pragma unroll
                for (int nt = 0; nt < 4; ++nt) {
                    int c0x = bc + wn + nt * 8 + 2 * t;
                    const float* a4 = acc[mt][nt];
                    #pragma unroll
                    for (int e = 0; e < 2; ++e) {
                        int cx = c0x + e;
                        if (cx < Mstore) {
                            float v0 = 0.f, v1 = 0.f;
                            if (cx < M) {
                                float bv = bias ? bias[cx] : 0.f;
                                v0 = a4[e] + bv;
                                v1 = a4[2 + e] + bv;
                            }
                            C[(long)r0 * ldC + cx] = v0;
                            C[(long)(r0 + 8) * ldC + cx] = v1;
                        }
                    }
                }
            }
        }
        __syncthreads();
    }
}

// ---------------- 128x128 tile GEMM: persistent + splitK (Wout/Wd) ----------
#define ASZ (128*XS)
__global__ void __launch_bounds__(256, 2) k_gemm_bf3(
        const __nv_bfloat16* __restrict__ Ah_, const __nv_bfloat16* __restrict__ Al_,
        const __nv_bfloat16* __restrict__ B1h_, const __nv_bfloat16* __restrict__ B1l_,
        float* __restrict__ C1, float* __restrict__ C2,
        int N, int K, int M, int tilesX, int ksplit) {
    extern __shared__ unsigned sm[];
    const unsigned* Ahw = (const unsigned*)Ah_;
    const unsigned* Alw = (const unsigned*)Al_;
    const unsigned* Bhw = (const unsigned*)B1h_;
    const unsigned* Blw = (const unsigned*)B1l_;
    int tid = threadIdx.x, wid = tid >> 5, lane = tid & 31;
    int wm = (wid & 1) * 64, wn = (wid >> 1) * 32;
    int Kw = K >> 1;
    int NC = Kw >> 4;
    int NCH = NC / ksplit;
    unsigned sbase = (unsigned)__cvta_generic_to_shared(sm);
    int tilesY = N >> 7;
    int per = tilesX * tilesY;
    int total = per * ksplit;

    int lrow0 = tid >> 2, lw4 = (tid & 3) * 4;
    int lrow1 = lrow0 + 64;
    int rq   = lane & 7;
    int a_r  = rq + ((lane >> 3) & 1) * 8;
    int a_wo = ((lane >> 4) << 2);
    int b_r  = rq + ((lane >> 4) << 3);
    int b_wo = (((lane >> 3) & 1) << 2);
    int g = lane >> 2, t = lane & 3;

    for (int tI = blockIdx.x; tI < total; tI += gridDim.x) {
        int sel = (tI >= per) ? 1 : 0;
        int tt = sel ? tI - per : tI;
        int by = tt / tilesX, bx = tt - by * tilesX;
        int br = by * 128, bc = bx * 128;
        float* C = sel ? C2 : C1;
        int c0 = sel ? NCH : 0;

        int brow0 = bc + lrow0; if (brow0 >= M) brow0 = M - 1;
        int brow1 = bc + lrow1; if (brow1 >= M) brow1 = M - 1;
        float acc[4][4][4] = {};

        auto load_chunk = [&](int c, int stage) {
            int kw = c * 16 + lw4;
            unsigned sb = sbase + (unsigned)stage * (4u * ASZ * 4u);
            unsigned d0 = sb + (lrow0 * XS + lw4) * 4u;
            unsigned d1 = sb + (lrow1 * XS + lw4) * 4u;
            long a0 = (long)(br + lrow0) * Kw + kw;
            long a1 = (long)(br + lrow1) * Kw + kw;
            long b0 = (long)brow0 * Kw + kw;
            long b1 = (long)brow1 * Kw + kw;
            cp16(d0,                 Ahw + a0);
            cp16(d1,                 Ahw + a1);
            cp16(d0 + ASZ * 4u,      Alw + a0);
            cp16(d1 + ASZ * 4u,      Alw + a1);
            cp16(d0 + 2u * ASZ * 4u, Bhw + b0);
            cp16(d1 + 2u * ASZ * 4u, Bhw + b1);
            cp16(d0 + 3u * ASZ * 4u, Blw + b0);
            cp16(d1 + 3u * ASZ * 4u, Blw + b1);
            cp_commit();
        };

        load_chunk(c0, 0);

        for (int cl = 0; cl < NCH; ++cl) {
            if (cl + 1 < NCH) {
                load_chunk(c0 + cl + 1, (cl + 1) & 1);
                cp_wait<1>();
            } else {
                cp_wait<0>();
            }
            __syncthreads();
            unsigned stg = sbase + (unsigned)(cl & 1) * (4u * ASZ * 4u);
            unsigned aAh = stg;
            unsigned aAl = stg + ASZ * 4u;
            unsigned aBh = stg + 2u * ASZ * 4u;
            unsigned aBl = stg + 3u * ASZ * 4u;
            #pragma unroll
            for (int ks = 0; ks < 2; ++ks) {
                int kpb = ks * 8;
                unsigned ah[4][4], al[4][4], bh[4][2], bl[4][2];
                #pragma unroll
                for (int mt = 0; mt < 4; ++mt) {
                    unsigned off = (unsigned)(((wm + mt * 16 + a_r) * XS + kpb + a_wo) * 4);
                    ldsm4(ah[mt][0], ah[mt][1], ah[mt][2], ah[mt][3], aAh + off);
                    ldsm4(al[mt][0], al[mt][1], al[mt][2], al[mt][3], aAl + off);
                }
                #pragma unroll
                for (int p = 0; p < 2; ++p) {
                    unsigned off = (unsigned)(((wn + p * 16 + b_r) * XS + kpb + b_wo) * 4);
                    ldsm4(bh[2*p][0], bh[2*p][1], bh[2*p+1][0], bh[2*p+1][1], aBh + off);
                    ldsm4(bl[2*p][0], bl[2*p][1], bl[2*p+1][0], bl[2*p+1][1], aBl + off);
                }
                #pragma unroll
                for (int mt = 0; mt < 4; ++mt)
                    #pragma unroll
                    for (int nt = 0; nt < 4; ++nt) {
                        mma_bf16(acc[mt][nt], ah[mt], bh[nt], acc[mt][nt]);
                        mma_bf16(acc[mt][nt], ah[mt], bl[nt], acc[mt][nt]);
                        mma_bf16(acc[mt][nt], al[mt], bh[nt], acc[mt][nt]);
                    }
            }
            __syncthreads();
        }

        #pragma unroll
        for (int mt = 0; mt < 4; ++mt) {
            int r0 = br + wm + mt * 16 + g;
            #pragma unroll
            for (int nt = 0; nt < 4; ++nt) {
                int c0x = bc + wn + nt * 8 + 2 * t;
                const float* a4 = acc[mt][nt];
                #pragma unroll
                for (int e = 0; e < 2; ++e) {
                    int cx = c0x + e;
                    C[(long)r0 * M + cx] = a4[e];
                    C[(long)(r0 + 8) * M + cx] = a4[2 + e];
                }
            }
        }
        __syncthreads();
    }
}

// ---------------- flash attention (unchanged) -------------------------------
#define FWPA 2304
#define FSTG (4*FWPA)
__global__ void __launch_bounds__(128) k_flash(
        const __nv_bfloat16* __restrict__ qh_, const __nv_bfloat16* __restrict__ ql_,
        const __nv_bfloat16* __restrict__ kh_, const __nv_bfloat16* __restrict__ kl_,
        const __nv_bfloat16* __restrict__ vh_, const __nv_bfloat16* __restrict__ vl_,
        __nv_bfloat16* __restrict__ oh_, __nv_bfloat16* __restrict__ ol_) {
    extern __shared__ unsigned fsm[];
    int qt = (int)gridDim.x - 1 - blockIdx.x;
    int bh = blockIdx.y;
    int tid = threadIdx.x, wid = tid >> 5, lane = tid & 31;
    int g = lane >> 2, t = lane & 3;
    const unsigned* qhw = (const unsigned*)qh_;
    const unsigned* qlw = (const unsigned*)ql_;
    const unsigned* khw = (const unsigned*)kh_;
    const unsigned* klw = (const unsigned*)kl_;
    const unsigned* vhw = (const unsigned*)vh_;
    const unsigned* vlw = (const unsigned*)vl_;
    unsigned sb = (unsigned)__cvta_generic_to_shared(fsm);

    int rq  = lane & 7;
    int b_r = rq + ((lane >> 4) << 3);
    int b_wo = (((lane >> 3) & 1) << 2);
    int v_r = rq + ((lane >> 3) & 1) * 8;
    int v_c = (lane >> 4) << 2;

    long qbase = ((long)bh * SD + qt * 64) * 32;
    #pragma unroll
    for (int it = 0; it < 16; ++it) {
        int idx = tid + it * 128;
        int row = idx >> 5, col = idx & 31;
        fsm[row * 36 + col]        = qhw[qbase + row * 32 + col];
        fsm[FWPA + row * 36 + col] = qlw[qbase + row * 32 + col];
    }
    __syncthreads();
    int r0 = wid * 16 + g;
    unsigned qfh[4][4], qfl[4][4];
    #pragma unroll
    for (int kk = 0; kk < 4; ++kk) {
        qfh[kk][0] = fsm[r0 * 36 + kk * 8 + t];
        qfh[kk][1] = fsm[(r0 + 8) * 36 + kk * 8 + t];
        qfh[kk][2] = fsm[r0 * 36 + kk * 8 + t + 4];
        qfh[kk][3] = fsm[(r0 + 8) * 36 + kk * 8 + t + 4];
        qfl[kk][0] = fsm[FWPA + r0 * 36 + kk * 8 + t];
        qfl[kk][1] = fsm[FWPA + (r0 + 8) * 36 + kk * 8 + t];
        qfl[kk][2] = fsm[FWPA + r0 * 36 + kk * 8 + t + 4];
        qfl[kk][3] = fsm[FWPA + (r0 + 8) * 36 + kk * 8 + t + 4];
    }
    __syncthreads();

    auto loadKV = [&](int kt, int stg) {
        long kb = ((long)bh * SD + kt * 64) * 32;
        unsigned base = sb + (unsigned)stg * (FSTG * 4u);
        #pragma unroll
        for (int it = 0; it < 4; ++it) {
            int idx = tid + it * 128;
            int row = idx >> 3, wg = (idx & 7) * 4;
            unsigned d = base + (unsigned)(row * 36 + wg) * 4u;
            long gsrc = kb + row * 32 + wg;
            cp16(d,                   khw + gsrc);
            cp16(d + FWPA * 4u,       klw + gsrc);
            cp16(d + 2u * FWPA * 4u,  vhw + gsrc);
            cp16(d + 3u * FWPA * 4u,  vlw + gsrc);
        }
        cp_commit();
    };

    float m0 = -INFINITY, m1 = -INFINITY, l0 = 0.f, l1 = 0.f;
    float od[8][4] = {};

    loadKV(0, 0);
    for (int kt = 0; kt <= qt; ++kt) {
        if (kt + 1 <= qt) {
            loadKV(kt + 1, (kt + 1) & 1);
            cp_wait<1>();
        } else {
            cp_wait<0>();
        }
        __syncthreads();
        unsigned stg = sb + (unsigned)(kt & 1) * (FSTG * 4u);
        unsigned aKh = stg;
        unsigned aKl = stg + FWPA * 4u;
        unsigned aVh = stg + 2u * FWPA * 4u;
        unsigned aVl = stg + 3u * FWPA * 4u;

        float sacc[8][4] = {};
        #pragma unroll
        for (int kk = 0; kk < 4; ++kk) {
            unsigned kbh[8][2], kbl[8][2];
            #pragma unroll
            for (int p = 0; p < 4; ++p) {
                unsigned off = (unsigned)(((p * 16 + b_r) * 36 + kk * 8 + b_wo) * 4);
                ldsm4(kbh[2*p][0], kbh[2*p][1], kbh[2*p+1][0], kbh[2*p+1][1], aKh + off);
                ldsm4(kbl[2*p][0], kbl[2*p][1], kbl[2*p+1][0], kbl[2*p+1][1], aKl + off);
            }
            #pragma unroll
            for (int nt = 0; nt < 8; ++nt) {
                mma_bf16(sacc[nt], qfh[kk], kbh[nt], sacc[nt]);
                mma_bf16(sacc[nt], qfh[kk], kbl[nt], sacc[nt]);
                mma_bf16(sacc[nt], qfl[kk], kbh[nt], sacc[nt]);
            }
        }
        #pragma unroll
        for (int nt = 0; nt < 8; ++nt) {
            #pragma unroll
            for (int e = 0; e < 4; ++e) sacc[nt][e] *= 0.125f;
        }
        if (kt == qt) {
            #pragma unroll
            for (int nt = 0; nt < 8; ++nt) {
                int c = nt * 8 + 2 * t;
                if (c > r0)         sacc[nt][0] = -1e30f;
                if (c + 1 > r0)     sacc[nt][1] = -1e30f;
                if (c > r0 + 8)     sacc[nt][2] = -1e30f;
                if (c + 1 > r0 + 8) sacc[nt][3] = -1e30f;
            }
        }
        float tm0 = -1e30f, tm1 = -1e30f;
        #pragma unroll
        for (int nt = 0; nt < 8; ++nt) {
            tm0 = fmaxf(tm0, fmaxf(sacc[nt][0], sacc[nt][1]));
            tm1 = fmaxf(tm1, fmaxf(sacc[nt][2], sacc[nt][3]));
        }
        tm0 = fmaxf(tm0, __shfl_xor_sync(0xffffffffu, tm0, 1));
        tm0 = fmaxf(tm0, __shfl_xor_sync(0xffffffffu, tm0, 2));
        tm1 = fmaxf(tm1, __shfl_xor_sync(0xffffffffu, tm1, 1));
        tm1 = fmaxf(tm1, __shfl_xor_sync(0xffffffffu, tm1, 2));
        float mn0 = fmaxf(m0, tm0), mn1 = fmaxf(m1, tm1);
        float sc0 = __expf(m0 - mn0), sc1 = __expf(m1 - mn1);
        m0 = mn0; m1 = mn1;
        l0 *= sc0; l1 *= sc1;
        #pragma unroll
        for (int nt = 0; nt < 8; ++nt) {
            od[nt][0] *= sc0; od[nt][1] *= sc0;
            od[nt][2] *= sc1; od[nt][3] *= sc1;
        }
        #pragma unroll
        for (int nt = 0; nt < 8; ++nt) {
            sacc[nt][0] = __expf(sacc[nt][0] - m0);
            sacc[nt][1] = __expf(sacc[nt][1] - m0);
            sacc[nt][2] = __expf(sacc[nt][2] - m1);
            sacc[nt][3] = __expf(sacc[nt][3] - m1);
            l0 += sacc[nt][0] + sacc[nt][1];
            l1 += sacc[nt][2] + sacc[nt][3];
        }
        unsigned pah[4][4], pal[4][4];
        #pragma unroll
        for (int kk = 0; kk < 4; ++kk) {
            pack_split2(sacc[2*kk][0],   sacc[2*kk][1],   pah[kk][0], pal[kk][0]);
            pack_split2(sacc[2*kk][2],   sacc[2*kk][3],   pah[kk][1], pal[kk][1]);
            pack_split2(sacc[2*kk+1][0], sacc[2*kk+1][1], pah[kk][2], pal[kk][2]);
            pack_split2(sacc[2*kk+1][2], sacc[2*kk+1][3], pah[kk][3], pal[kk][3]);
        }
        #pragma unroll
        for (int kk = 0; kk < 4; ++kk) {
            unsigned vbh[8][2], vbl[8][2];
            #pragma unroll
            for (int p = 0; p < 4; ++p) {
                unsigned off = (unsigned)(((kk * 16 + v_r) * 36 + p * 8 + v_c) * 4);
                ldsm4t(vbh[2*p][0], vbh[2*p][1], vbh[2*p+1][0], vbh[2*p+1][1], aVh + off);
                ldsm4t(vbl[2*p][0], vbl[2*p][1], vbl[2*p+1][0], vbl[2*p+1][1], aVl + off);
            }
            #pragma unroll
            for (int nt = 0; nt < 8; ++nt) {
                mma_bf16(od[nt], pah[kk], vbh[nt], od[nt]);
                mma_bf16(od[nt], pah[kk], vbl[nt], od[nt]);
                mma_bf16(od[nt], pal[kk], vbh[nt], od[nt]);
            }
        }
        __syncthreads();
    }

    l0 += __shfl_xor_sync(0xffffffffu, l0, 1);
    l0 += __shfl_xor_sync(0xffffffffu, l0, 2);
    l1 += __shfl_xor_sync(0xffffffffu, l1, 1);
    l1 += __shfl_xor_sync(0xffffffffu, l1, 2);
    float i0 = 1.f / l0, i1 = 1.f / l1;
    int b = bh >> 4, h = bh & 15;
    long ob0 = ((long)(b * SD + qt * 64 + r0)) * DD + h * HDIM;
    long ob1 = ob0 + 8L * DD;
    #pragma unroll
    for (int nt = 0; nt < 8; ++nt) {
        int d = nt * 8 + 2 * t;
        __nv_bfloat16 hh, ll;
        split_bf(od[nt][0] * i0, hh, ll); oh_[ob0 + d] = hh;     ol_[ob0 + d] = ll;
        split_bf(od[nt][1] * i0, hh, ll); oh_[ob0 + d + 1] = hh; ol_[ob0 + d + 1] = ll;
        split_bf(od[nt][2] * i1, hh, ll); oh_[ob1 + d] = hh;     ol_[ob1 + d] = ll;
        split_bf(od[nt][3] * i1, hh, ll); oh_[ob1 + d + 1] = hh; ol_[ob1 + d + 1] = ll;
    }
}

// ---------------- SwiGLU vectorized -----------------------------------------
__global__ void k_silu(const float* __restrict__ g, const float* __restrict__ u,
                       __nv_bfloat16* __restrict__ oh, __nv_bfloat16* __restrict__ ol) {
    int idx = blockIdx.x * 256 + threadIdx.x;
    int row = idx / (MP / 4);
    int c4 = (idx - row * (MP / 4)) * 4;
    long base = (long)row * MP + c4;
    float4 gv = *(const float4*)(g + base);
    float4 uv = *(const float4*)(u + base);
    float v0 = (gv.x / (1.f + expf(-gv.x))) * uv.x;
    float v1 = (gv.y / (1.f + expf(-gv.y))) * uv.y;
    float v2 = (gv.z / (1.f + expf(-gv.z))) * uv.z;
    float v3 = (gv.w / (1.f + expf(-gv.w))) * uv.w;
    unsigned h0, l0, h1, l1;
    pack_split2(v0, v1, h0, l0);
    pack_split2(v2, v3, h1, l1);
    ((unsigned*)oh)[base >> 1] = h0;
    ((unsigned*)oh)[(base >> 1) + 1] = h1;
    ((unsigned*)ol)[base >> 1] = l0;
    ((unsigned*)ol)[(base >> 1) + 1] = l1;
}

// ---------------- head --------------------------------------------------------
__global__ void __launch_bounds__(256) k_head(const __nv_bfloat16* __restrict__ hh,
                                              const __nv_bfloat16* __restrict__ hl,
                                              const float* __restrict__ W,
                                              const float* __restrict__ bias,
                                              float* __restrict__ out) {
    int bidx = blockIdx.y;
    int col = blockIdx.x * 256 + threadIdx.x;
    __shared__ float sx[DD];
    long roff = (long)(bidx * SD + SD - 1) * DD;
    for (int c = threadIdx.x; c < DD; c += 256)
        sx[c] = __bfloat162float(hh[roff + c]) + __bfloat162float(hl[roff + c]);
    __syncthreads();
    if (col >= VV) return;
    float acc = 0.f;
    #pragma unroll 8
    for (int k = 0; k < DD; ++k) acc += sx[k] * W[(long)k * VV + col];
    out[(long)bidx * VV + col] = acc + bias[col];
}

// ---------------- driver -----------------------------------------------------
extern "C" void kernel_launch(void* const* d_in, const int* in_sizes, int n_in,
                              void* d_out, int out_size) {
    const int*   tokens = (const int*)  d_in[0];
    const float* embed  = (const float*)d_in[1];
    const float* Wqkv   = (const float*)d_in[2];
    const float* bqkv   = (const float*)d_in[3];
    const float* Wout   = (const float*)d_in[4];
    const float* bout   = (const float*)d_in[5];
    const float* ln1    = (const float*)d_in[6];
    const float* ln2    = (const float*)d_in[7];
    const float* Wg     = (const float*)d_in[8];
    const float* bg     = (const float*)d_in[9];
    const float* Wu     = (const float*)d_in[10];
    const float* bu     = (const float*)d_in[11];
    const float* Wd     = (const float*)d_in[12];
    const float* bd     = (const float*)d_in[13];
    const float* lnf    = (const float*)d_in[14];
    const float* Whead  = (const float*)d_in[15];
    const float* bhead  = (const float*)d_in[16];
    float* out = (float*)d_out;

    float *x, *gate, *up;
    __nv_bfloat16 *hh, *hl, *ath, *atl, *gth, *gtl;
    __nv_bfloat16 *qh, *ql, *kh, *kl, *vh, *vl;
    __nv_bfloat16 *wqkvh, *wqkvl, *wouth, *woutl, *wgh, *wgl, *wuh, *wul, *wdh, *wdl;
    cudaGetSymbolAddress((void**)&x,    g_x);
    cudaGetSymbolAddress((void**)&gate, g_gate);
    cudaGetSymbolAddress((void**)&up,   g_up);
    cudaGetSymbolAddress((void**)&hh,   g_h_h);
    cudaGetSymbolAddress((void**)&hl,   g_h_l);
    cudaGetSymbolAddress((void**)&ath,  g_attn_h);
    cudaGetSymbolAddress((void**)&atl,  g_attn_l);
    cudaGetSymbolAddress((void**)&gth,  g_gate_h);
    cudaGetSymbolAddress((void**)&gtl,  g_gate_l);
    cudaGetSymbolAddress((void**)&qh,   g_q_h);
    cudaGetSymbolAddress((void**)&ql,   g_q_l);
    cudaGetSymbolAddress((void**)&kh,   g_k_h);
    cudaGetSymbolAddress((void**)&kl,   g_k_l);
    cudaGetSymbolAddress((void**)&vh,   g_v_h);
    cudaGetSymbolAddress((void**)&vl,   g_v_l);
    cudaGetSymbolAddress((void**)&wqkvh, g_wqkvT_h);
    cudaGetSymbolAddress((void**)&wqkvl, g_wqkvT_l);
    cudaGetSymbolAddress((void**)&wouth, g_woutT_h);
    cudaGetSymbolAddress((void**)&woutl, g_woutT_l);
    cudaGetSymbolAddress((void**)&wgh,  g_wgT_h);
    cudaGetSymbolAddress((void**)&wgl,  g_wgT_l);
    cudaGetSymbolAddress((void**)&wuh,  g_wuT_h);
    cudaGetSymbolAddress((void**)&wul,  g_wuT_l);
    cudaGetSymbolAddress((void**)&wdh,  g_wdT_h);
    cudaGetSymbolAddress((void**)&wdl,  g_wdT_l);

    cudaFuncSetAttribute(k_gemm_bf3, cudaFuncAttributeMaxDynamicSharedMemorySize, 81920);
    cudaFuncSetAttribute(k_gemm64, cudaFuncAttributeMaxDynamicSharedMemorySize, 2 * STG64 * 4);
    cudaFuncSetAttribute(k_flash, cudaFuncAttributeMaxDynamicSharedMemorySize, 2 * FSTG * 4);
    const int GSM = 81920;
    const int GSM64 = 2 * STG64 * 4;
    const int FSM = 2 * FSTG * 4;
    const int PBLK = 296;
    float* p0 = gate;
    float* p1 = up;

    dim3 tb(32, 8);
    k_wsplit<<<dim3(96, 16, LL), tb>>>(Wqkv, wqkvh, wqkvl, DD, 3 * DD, DD,
                                       (long)DD * 3 * DD, (long)3 * DD * DD);
    k_wsplit<<<dim3(32, 16, LL), tb>>>(Wout, wouth, woutl, DD, DD, DD,
                                       (long)DD * DD, (long)DD * DD);
    k_wsplit<<<dim3(86, 16, LL), tb>>>(Wg, wgh, wgl, DD, MMF, DD,
                                       (long)DD * MMF, (long)MMF * DD);
    k_wsplit<<<dim3(86, 16, LL), tb>>>(Wu, wuh, wul, DD, MMF, DD,
                                       (long)DD * MMF, (long)MMF * DD);
    k_wsplit<<<dim3(32, 43, LL), tb>>>(Wd, wdh, wdl, MMF, DD, MP,
                                       (long)MMF * DD, (long)DD * MP);

    k_embed<<<NTOK, 256>>>(tokens, embed, x);
    k_rmsnorm<<<NTOK, 256>>>(x, ln1, hh, hl);

    for (int l = 0; l < LL; ++l) {
        // QKV 64-row tiles with fused rope/split epilogue: 24x32 = 768 tiles
        k_gemm64<<<PBLK, 256, GSM64>>>(hh, hl,
                                wqkvh + (long)l * 3 * DD * DD, wqkvl + (long)l * 3 * DD * DD,
                                bqkv + (long)l * 3 * DD, nullptr,
                                nullptr, nullptr, nullptr, nullptr,
                                NTOK, DD, 3 * DD, 24, 3 * DD, 3 * DD, 1,
                                qh, ql, kh, kl, vh, vl);

        k_flash<<<dim3(SD / 64, BH), 128, FSM>>>(qh, ql, kh, kl, vh, vl, ath, atl);

        // Wout split-K=2 -> p0,p1
        k_gemm_bf3<<<256, 256, GSM>>>(ath, atl,
                                wouth + (long)l * DD * DD, woutl + (long)l * DD * DD,
                                p0, p1, NTOK, DD, DD, 8, 2);
        k_comb_rms<<<NTOK, 256>>>(x, p0, p1, bout + (long)l * DD,
                                  ln2 + (long)l * DD, hh, hl);

        // Wg + Wu dual, 64-row tiles: 2 x (22x32) = 1408 tiles
        k_gemm64<<<PBLK, 256, GSM64>>>(hh, hl,
                                wgh + (long)l * MMF * DD, wgl + (long)l * MMF * DD,
                                bg + (long)l * MMF, gate,
                                wuh + (long)l * MMF * DD, wul + (long)l * MMF * DD,
                                bu + (long)l * MMF, up,
                                NTOK, DD, MMF, 22, MP, MP, 0,
                                nullptr, nullptr, nullptr, nullptr, nullptr, nullptr);

        k_silu<<<NTOK * (MP / 4) / 256, 256>>>(gate, up, gth, gtl);

        // Wd split-K=2 -> p0,p1
        k_gemm_bf3<<<256, 256, GSM>>>(gth, gtl,
                                wdh + (long)l * DD * MP, wdl + (long)l * DD * MP,
                                p0, p1, NTOK, MP, DD, 8, 2);
        const float* wnext = (l < LL - 1) ? (ln1 + (long)(l + 1) * DD) : lnf;
        k_comb_rms<<<NTOK, 256>>>(x, p0, p1, bd + (long)l * DD, wnext, hh, hl);
    }

    dim3 gh((VV + 255) / 256, BD);
    k_head<<<gh, 256>>>(hh, hl, Whead, bhead, out);
}

// round 14
// speedup vs baseline: 1.0664x; 1.0664x over previous
#include <cuda_runtime.h>
#include <cuda_bf16.h>
#include <math.h>

#define BD   2
#define SD   1024
#define DD   1024
#define HH   16
#define HDIM 64
#define LL   4
#define MMF  2730
#define MP   2752
#define VV   32000
#define NTOK (BD*SD)
#define BH   (BD*HH)

// ---------------- scratch (device globals; no allocation allowed) ----------
__device__ float g_x[NTOK*DD];
__device__ float g_gate[(long)NTOK*MP];     // also reused as split-K partial p0
__device__ float g_up[(long)NTOK*MP];       // also reused as split-K partial p1

__device__ __nv_bfloat16 g_h_h[NTOK*DD],    g_h_l[NTOK*DD];
__device__ __nv_bfloat16 g_attn_h[NTOK*DD], g_attn_l[NTOK*DD];
__device__ __nv_bfloat16 g_gate_h[NTOK*MP], g_gate_l[NTOK*MP];

__device__ __nv_bfloat16 g_q_h[BH*SD*HDIM], g_q_l[BH*SD*HDIM];
__device__ __nv_bfloat16 g_k_h[BH*SD*HDIM], g_k_l[BH*SD*HDIM];
__device__ __nv_bfloat16 g_v_h[BH*SD*HDIM], g_v_l[BH*SD*HDIM];

__device__ __nv_bfloat16 g_wqkvT_h[LL*3*DD*DD], g_wqkvT_l[LL*3*DD*DD];
__device__ __nv_bfloat16 g_woutT_h[LL*DD*DD],   g_woutT_l[LL*DD*DD];
__device__ __nv_bfloat16 g_wgT_h[LL*MMF*DD],    g_wgT_l[LL*MMF*DD];
__device__ __nv_bfloat16 g_wuT_h[LL*MMF*DD],    g_wuT_l[LL*MMF*DD];
__device__ __nv_bfloat16 g_wdT_h[(long)LL*DD*MP], g_wdT_l[(long)LL*DD*MP];

// ---------------- helpers ----------------------------------------------------
__device__ __forceinline__ void split_bf(float f, __nv_bfloat16& h, __nv_bfloat16& l) {
    h = __float2bfloat16(f);
    l = __float2bfloat16(f - __bfloat162float(h));
}
__device__ __forceinline__ void pack_split2(float a, float b, unsigned& hi, unsigned& lo) {
    __nv_bfloat162 th, tl;
    th.x = __float2bfloat16(a);
    th.y = __float2bfloat16(b);
    tl.x = __float2bfloat16(a - __bfloat162float(th.x));
    tl.y = __float2bfloat16(b - __bfloat162float(th.y));
    hi = *(unsigned*)&th;
    lo = *(unsigned*)&tl;
}
__device__ __forceinline__ void mma_bf16(float* d, const unsigned* a,
                                         const unsigned* b, const float* c) {
    asm volatile(
        "mma.sync.aligned.m16n8k16.row.col.f32.bf16.bf16.f32 "
        "{%0,%1,%2,%3}, {%4,%5,%6,%7}, {%8,%9}, {%10,%11,%12,%13};"
        : "=f"(d[0]), "=f"(d[1]), "=f"(d[2]), "=f"(d[3])
        : "r"(a[0]), "r"(a[1]), "r"(a[2]), "r"(a[3]),
          "r"(b[0]), "r"(b[1]),
          "f"(c[0]), "f"(c[1]), "f"(c[2]), "f"(c[3]));
}
__device__ __forceinline__ void ldsm4(unsigned& r0, unsigned& r1, unsigned& r2,
                                      unsigned& r3, unsigned addr) {
    asm volatile("ldmatrix.sync.aligned.m8n8.x4.shared.b16 {%0,%1,%2,%3}, [%4];"
                 : "=r"(r0), "=r"(r1), "=r"(r2), "=r"(r3) : "r"(addr));
}
__device__ __forceinline__ void ldsm4t(unsigned& r0, unsigned& r1, unsigned& r2,
                                       unsigned& r3, unsigned addr) {
    asm volatile("ldmatrix.sync.aligned.m8n8.x4.trans.shared.b16 {%0,%1,%2,%3}, [%4];"
                 : "=r"(r0), "=r"(r1), "=r"(r2), "=r"(r3) : "r"(addr));
}
__device__ __forceinline__ void cp16(unsigned saddr, const void* g) {
    asm volatile("cp.async.cg.shared.global [%0], [%1], 16;" :: "r"(saddr), "l"(g));
}
__device__ __forceinline__ void cp_commit() {
    asm volatile("cp.async.commit_group;");
}
template<int N> __device__ __forceinline__ void cp_wait() {
    asm volatile("cp.async.wait_group %0;" :: "n"(N));
}

// ---------------- weight transpose + bf16 split ------------------------------
__global__ void k_wsplit(const float* __restrict__ W,
                         __nv_bfloat16* __restrict__ Th,
                         __nv_bfloat16* __restrict__ Tl,
                         int K, int M, int KP, long wstride, long tstride) {
    W  += (long)blockIdx.z * wstride;
    Th += (long)blockIdx.z * tstride;
    Tl += (long)blockIdx.z * tstride;
    __shared__ float t[64][33];
    int m0 = blockIdx.x * 32, k0 = blockIdx.y * 64;
    int tx = threadIdx.x, ty = threadIdx.y;
    #pragma unroll
    for (int i = 0; i < 64; i += 8) {
        int k = k0 + ty + i, m = m0 + tx;
        t[ty + i][tx] = (k < K && m < M) ? W[(long)k * M + m] : 0.f;
    }
    __syncthreads();
    #pragma unroll
    for (int i = 0; i < 32; i += 8) {
        int m = m0 + ty + i, kk = k0 + tx * 2;
        if (m < M && kk < KP) {
            __nv_bfloat16 h0, l0, h1, l1;
            split_bf(t[tx * 2][ty + i], h0, l0);
            split_bf(t[tx * 2 + 1][ty + i], h1, l1);
            __nv_bfloat162 ph; ph.x = h0; ph.y = h1;
            __nv_bfloat162 pl; pl.x = l0; pl.y = l1;
            ((unsigned*)Th)[((long)m * KP + kk) >> 1] = *(unsigned*)&ph;
            ((unsigned*)Tl)[((long)m * KP + kk) >> 1] = *(unsigned*)&pl;
        }
    }
}

__global__ void k_embed(const int* __restrict__ tok, const float* __restrict__ emb,
                        float* __restrict__ x) {
    int i = blockIdx.x * 256 + threadIdx.x;
    int n = i >> 8, c4 = (i & 255) * 4;
    *(float4*)(x + (long)n * DD + c4) =
        *(const float4*)(emb + (long)tok[n] * DD + c4);
}

__global__ void __launch_bounds__(256) k_rmsnorm(const float* __restrict__ x,
                                                 const float* __restrict__ w,
                                                 __nv_bfloat16* __restrict__ oh,
                                                 __nv_bfloat16* __restrict__ ol) {
    int row = blockIdx.x;
    int c4 = threadIdx.x * 4;
    float4 xv = *(const float4*)(x + (long)row * DD + c4);
    float s = xv.x * xv.x + xv.y * xv.y + xv.z * xv.z + xv.w * xv.w;
    __shared__ float red[8];
    #pragma unroll
    for (int off = 16; off; off >>= 1) s += __shfl_xor_sync(0xffffffffu, s, off);
    if ((threadIdx.x & 31) == 0) red[threadIdx.x >> 5] = s;
    __syncthreads();
    if (threadIdx.x == 0) {
        float tt = 0.f;
        #pragma unroll
        for (int i = 0; i < 8; ++i) tt += red[i];
        red[0] = tt;
    }
    __syncthreads();
    float r = rsqrtf(red[0] * (1.0f / DD) + 1e-6f);
    float4 wv = *(const float4*)(w + c4);
    unsigned h0, l0, h1, l1;
    pack_split2(xv.x * r * wv.x, xv.y * r * wv.y, h0, l0);
    pack_split2(xv.z * r * wv.z, xv.w * r * wv.w, h1, l1);
    long wi = ((long)row * DD + c4) >> 1;
    ((unsigned*)oh)[wi] = h0;
    ((unsigned*)oh)[wi + 1] = h1;
    ((unsigned*)ol)[wi] = l0;
    ((unsigned*)ol)[wi + 1] = l1;
}

// ---- combine split-K partials + residual + bias, then rmsnorm -> bf16 split -
__global__ void __launch_bounds__(256) k_comb_rms(float* __restrict__ x,
                                                  const float* __restrict__ p0,
                                                  const float* __restrict__ p1,
                                                  const float* __restrict__ bias,
                                                  const float* __restrict__ w,
                                                  __nv_bfloat16* __restrict__ oh,
                                                  __nv_bfloat16* __restrict__ ol) {
    int row = blockIdx.x;
    int c4 = threadIdx.x * 4;
    long base = (long)row * DD + c4;
    float4 xv = *(float4*)(x + base);
    float4 a = *(const float4*)(p0 + base);
    float4 b = *(const float4*)(p1 + base);
    float4 bv = *(const float4*)(bias + c4);
    xv.x += a.x + b.x + bv.x;
    xv.y += a.y + b.y + bv.y;
    xv.z += a.z + b.z + bv.z;
    xv.w += a.w + b.w + bv.w;
    *(float4*)(x + base) = xv;
    float s = xv.x * xv.x + xv.y * xv.y + xv.z * xv.z + xv.w * xv.w;
    __shared__ float red[8];
    #pragma unroll
    for (int off = 16; off; off >>= 1) s += __shfl_xor_sync(0xffffffffu, s, off);
    if ((threadIdx.x & 31) == 0) red[threadIdx.x >> 5] = s;
    __syncthreads();
    if (threadIdx.x == 0) {
        float tt = 0.f;
        #pragma unroll
        for (int i = 0; i < 8; ++i) tt += red[i];
        red[0] = tt;
    }
    __syncthreads();
    float r = rsqrtf(red[0] * (1.0f / DD) + 1e-6f);
    float4 wv = *(const float4*)(w + c4);
    unsigned h0, l0, h1, l1;
    pack_split2(xv.x * r * wv.x, xv.y * r * wv.y, h0, l0);
    pack_split2(xv.z * r * wv.z, xv.w * r * wv.w, h1, l1);
    long wi = base >> 1;
    ((unsigned*)oh)[wi] = h0;
    ((unsigned*)oh)[wi + 1] = h1;
    ((unsigned*)ol)[wi] = l0;
    ((unsigned*)ol)[wi + 1] = l1;
}

// ---------------- bf16 split-3 GEMM: persistent + dual/splitK + qkv epilogue -
#define XS 20
#define ASZ (128*XS)
__global__ void __launch_bounds__(256, 2) k_gemm_bf3(
        const __nv_bfloat16* __restrict__ Ah_, const __nv_bfloat16* __restrict__ Al_,
        const __nv_bfloat16* __restrict__ B1h_, const __nv_bfloat16* __restrict__ B1l_,
        const float* __restrict__ bias1, const float* __restrict__ add,
        float* __restrict__ C1,
        const __nv_bfloat16* __restrict__ B2h_, const __nv_bfloat16* __restrict__ B2l_,
        const float* __restrict__ bias2, float* __restrict__ C2,
        int N, int K, int M, int tilesX, int ldC, int Mstore, int qkv_mode, int ksplit,
        __nv_bfloat16* qh, __nv_bfloat16* ql,
        __nv_bfloat16* kh, __nv_bfloat16* kl,
        __nv_bfloat16* vh, __nv_bfloat16* vl) {
    extern __shared__ unsigned sm[];
    const unsigned* Ahw = (const unsigned*)Ah_;
    const unsigned* Alw = (const unsigned*)Al_;
    int tid = threadIdx.x, wid = tid >> 5, lane = tid & 31;
    int wm = (wid & 1) * 64, wn = (wid >> 1) * 32;
    int Kw = K >> 1;
    int NC = Kw >> 4;
    int NCH = NC / ksplit;
    unsigned sbase = (unsigned)__cvta_generic_to_shared(sm);
    int tilesY = N >> 7;
    int per = tilesX * tilesY;
    int total = per * ((B2h_ || ksplit == 2) ? 2 : 1);

    int lrow0 = tid >> 2, lw4 = (tid & 3) * 4;
    int lrow1 = lrow0 + 64;
    int rq   = lane & 7;
    int a_r  = rq + ((lane >> 3) & 1) * 8;
    int a_wo = ((lane >> 4) << 2);
    int b_r  = rq + ((lane >> 4) << 3);
    int b_wo = (((lane >> 3) & 1) << 2);
    int g = lane >> 2, t = lane & 3;

    for (int tI = blockIdx.x; tI < total; tI += gridDim.x) {
        int sel = (tI >= per) ? 1 : 0;               // dual-B or K-half
        int tt = sel ? tI - per : tI;
        int by = tt / tilesX, bx = tt - by * tilesX;
        int br = by * 128, bc = bx * 128;
        const unsigned* Bhw = (const unsigned*)((B2h_ && sel) ? B2h_ : B1h_);
        const unsigned* Blw = (const unsigned*)((B2l_ && sel) ? B2l_ : B1l_);
        const float* bias = (B2h_ && sel) ? bias2 : bias1;
        float* C = sel ? C2 : C1;
        int c0 = (ksplit == 2 && sel) ? NCH : 0;

        int brow0 = bc + lrow0; if (brow0 >= M) brow0 = M - 1;
        int brow1 = bc + lrow1; if (brow1 >= M) brow1 = M - 1;
        float acc[4][4][4] = {};

        auto load_chunk = [&](int c, int stage) {
            int kw = c * 16 + lw4;
            unsigned sb = sbase + (unsigned)stage * (4u * ASZ * 4u);
            unsigned d0 = sb + (lrow0 * XS + lw4) * 4u;
            unsigned d1 = sb + (lrow1 * XS + lw4) * 4u;
            long a0 = (long)(br + lrow0) * Kw + kw;
            long a1 = (long)(br + lrow1) * Kw + kw;
            long b0 = (long)brow0 * Kw + kw;
            long b1 = (long)brow1 * Kw + kw;
            cp16(d0,                 Ahw + a0);
            cp16(d1,                 Ahw + a1);
            cp16(d0 + ASZ * 4u,      Alw + a0);
            cp16(d1 + ASZ * 4u,      Alw + a1);
            cp16(d0 + 2u * ASZ * 4u, Bhw + b0);
            cp16(d1 + 2u * ASZ * 4u, Bhw + b1);
            cp16(d0 + 3u * ASZ * 4u, Blw + b0);
            cp16(d1 + 3u * ASZ * 4u, Blw + b1);
            cp_commit();
        };

        load_chunk(c0, 0);

        for (int cl = 0; cl < NCH; ++cl) {
            if (cl + 1 < NCH) {
                load_chunk(c0 + cl + 1, (cl + 1) & 1);
                cp_wait<1>();
            } else {
                cp_wait<0>();
            }
            __syncthreads();
            unsigned stg = sbase + (unsigned)(cl & 1) * (4u * ASZ * 4u);
            unsigned aAh = stg;
            unsigned aAl = stg + ASZ * 4u;
            unsigned aBh = stg + 2u * ASZ * 4u;
            unsigned aBl = stg + 3u * ASZ * 4u;
            #pragma unroll
            for (int ks = 0; ks < 2; ++ks) {
                int kpb = ks * 8;
                unsigned ah[4][4], al[4][4], bh[4][2], bl[4][2];
                #pragma unroll
                for (int mt = 0; mt < 4; ++mt) {
                    unsigned off = (unsigned)(((wm + mt * 16 + a_r) * XS + kpb + a_wo) * 4);
                    ldsm4(ah[mt][0], ah[mt][1], ah[mt][2], ah[mt][3], aAh + off);
                    ldsm4(al[mt][0], al[mt][1], al[mt][2], al[mt][3], aAl + off);
                }
                #pragma unroll
                for (int p = 0; p < 2; ++p) {
                    unsigned off = (unsigned)(((wn + p * 16 + b_r) * XS + kpb + b_wo) * 4);
                    ldsm4(bh[2*p][0], bh[2*p][1], bh[2*p+1][0], bh[2*p+1][1], aBh + off);
                    ldsm4(bl[2*p][0], bl[2*p][1], bl[2*p+1][0], bl[2*p+1][1], aBl + off);
                }
                #pragma unroll
                for (int mt = 0; mt < 4; ++mt)
                    #pragma unroll
                    for (int nt = 0; nt < 4; ++nt) {
                        mma_bf16(acc[mt][nt], ah[mt], bh[nt], acc[mt][nt]);
                        mma_bf16(acc[mt][nt], ah[mt], bl[nt], acc[mt][nt]);
                        mma_bf16(acc[mt][nt], al[mt], bh[nt], acc[mt][nt]);
                    }
            }
            __syncthreads();
        }

        if (qkv_mode) {
            int sec = bc >> 10;
            #pragma unroll
            for (int nt = 0; nt < 4; ++nt) {
                int c0x = bc + wn + nt * 8 + 2 * t;
                int cc = c0x & 1023;
                int h = cc >> 6, j = (cc & 63) >> 1;
                float b0 = bias[c0x], b1 = bias[c0x + 1];
                float freq = exp2f(-0.41524101186f * (float)j);
                __nv_bfloat16* oh = (sec == 0) ? qh : (sec == 1) ? kh : vh;
                __nv_bfloat16* ol = (sec == 0) ? ql : (sec == 1) ? kl : vl;
                #pragma unroll
                for (int mt = 0; mt < 4; ++mt) {
                    #pragma unroll
                    for (int rr = 0; rr < 2; ++rr) {
                        int tok = br + wm + mt * 16 + g + rr * 8;
                        float e = acc[mt][nt][rr * 2 + 0] + b0;
                        float o = acc[mt][nt][rr * 2 + 1] + b1;
                        int s = tok & (SD - 1), b = tok >> 10;
                        if (sec < 2) {
                            float sn, cs;
                            sincosf((float)s * freq, &sn, &cs);
                            float e2 = e * cs - o * sn;
                            o = e * sn + o * cs;
                            e = e2;
                        }
                        long off = ((long)(b * HH + h) * SD + s) * 32 + j;
                        unsigned hi, lo;
                        pack_split2(e, o, hi, lo);
                        ((unsigned*)oh)[off] = hi;
                        ((unsigned*)ol)[off] = lo;
                    }
                }
            }
        } else {
            #pragma unroll
            for (int mt = 0; mt < 4; ++mt) {
                int r0 = br + wm + mt * 16 + g;
                #pragma unroll
                for (int nt = 0; nt < 4; ++nt) {
                    int c0x = bc + wn + nt * 8 + 2 * t;
                    const float* a4 = acc[mt][nt];
                    #pragma unroll
                    for (int e = 0; e < 2; ++e) {
                        int cx = c0x + e;
                        if (cx < Mstore) {
                            float v0, v1;
                            if (cx < M) {
                                float bv = bias ? bias[cx] : 0.f;
                                v0 = a4[e] + bv;
                                v1 = a4[2 + e] + bv;
                                if (add) {
                                    v0 += add[(long)r0 * ldC + cx];
                                    v1 += add[(long)(r0 + 8) * ldC + cx];
                                }
                            } else {
                                v0 = 0.f; v1 = 0.f;
                            }
                            C[(long)r0 * ldC + cx] = v0;
                            C[(long)(r0 + 8) * ldC + cx] = v1;
                        }
                    }
                }
            }
        }
        __syncthreads();
    }
}

// ---------------- flash attention (unchanged) -------------------------------
#define FWPA 2304
#define FSTG (4*FWPA)
__global__ void __launch_bounds__(128) k_flash(
        const __nv_bfloat16* __restrict__ qh_, const __nv_bfloat16* __restrict__ ql_,
        const __nv_bfloat16* __restrict__ kh_, const __nv_bfloat16* __restrict__ kl_,
        const __nv_bfloat16* __restrict__ vh_, const __nv_bfloat16* __restrict__ vl_,
        __nv_bfloat16* __restrict__ oh_, __nv_bfloat16* __restrict__ ol_) {
    extern __shared__ unsigned fsm[];
    int qt = (int)gridDim.x - 1 - blockIdx.x;
    int bh = blockIdx.y;
    int tid = threadIdx.x, wid = tid >> 5, lane = tid & 31;
    int g = lane >> 2, t = lane & 3;
    const unsigned* qhw = (const unsigned*)qh_;
    const unsigned* qlw = (const unsigned*)ql_;
    const unsigned* khw = (const unsigned*)kh_;
    const unsigned* klw = (const unsigned*)kl_;
    const unsigned* vhw = (const unsigned*)vh_;
    const unsigned* vlw = (const unsigned*)vl_;
    unsigned sb = (unsigned)__cvta_generic_to_shared(fsm);

    int rq  = lane & 7;
    int b_r = rq + ((lane >> 4) << 3);
    int b_wo = (((lane >> 3) & 1) << 2);
    int v_r = rq + ((lane >> 3) & 1) * 8;
    int v_c = (lane >> 4) << 2;

    long qbase = ((long)bh * SD + qt * 64) * 32;
    #pragma unroll
    for (int it = 0; it < 16; ++it) {
        int idx = tid + it * 128;
        int row = idx >> 5, col = idx & 31;
        fsm[row * 36 + col]        = qhw[qbase + row * 32 + col];
        fsm[FWPA + row * 36 + col] = qlw[qbase + row * 32 + col];
    }
    __syncthreads();
    int r0 = wid * 16 + g;
    unsigned qfh[4][4], qfl[4][4];
    #pragma unroll
    for (int kk = 0; kk < 4; ++kk) {
        qfh[kk][0] = fsm[r0 * 36 + kk * 8 + t];
        qfh[kk][1] = fsm[(r0 + 8) * 36 + kk * 8 + t];
        qfh[kk][2] = fsm[r0 * 36 + kk * 8 + t + 4];
        qfh[kk][3] = fsm[(r0 + 8) * 36 + kk * 8 + t + 4];
        qfl[kk][0] = fsm[FWPA + r0 * 36 + kk * 8 + t];
        qfl[kk][1] = fsm[FWPA + (r0 + 8) * 36 + kk * 8 + t];
        qfl[kk][2] = fsm[FWPA + r0 * 36 + kk * 8 + t + 4];
        qfl[kk][3] = fsm[FWPA + (r0 + 8) * 36 + kk * 8 + t + 4];
    }
    __syncthreads();

    auto loadKV = [&](int kt, int stg) {
        long kb = ((long)bh * SD + kt * 64) * 32;
        unsigned base = sb + (unsigned)stg * (FSTG * 4u);
        #pragma unroll
        for (int it = 0; it < 4; ++it) {
            int idx = tid + it * 128;
            int row = idx >> 3, wg = (idx & 7) * 4;
            unsigned d = base + (unsigned)(row * 36 + wg) * 4u;
            long gsrc = kb + row * 32 + wg;
            cp16(d,                   khw + gsrc);
            cp16(d + FWPA * 4u,       klw + gsrc);
            cp16(d + 2u * FWPA * 4u,  vhw + gsrc);
            cp16(d + 3u * FWPA * 4u,  vlw + gsrc);
        }
        cp_commit();
    };

    float m0 = -INFINITY, m1 = -INFINITY, l0 = 0.f, l1 = 0.f;
    float od[8][4] = {};

    loadKV(0, 0);
    for (int kt = 0; kt <= qt; ++kt) {
        if (kt + 1 <= qt) {
            loadKV(kt + 1, (kt + 1) & 1);
            cp_wait<1>();
        } else {
            cp_wait<0>();
        }
        __syncthreads();
        unsigned stg = sb + (unsigned)(kt & 1) * (FSTG * 4u);
        unsigned aKh = stg;
        unsigned aKl = stg + FWPA * 4u;
        unsigned aVh = stg + 2u * FWPA * 4u;
        unsigned aVl = stg + 3u * FWPA * 4u;

        float sacc[8][4] = {};
        #pragma unroll
        for (int kk = 0; kk < 4; ++kk) {
            unsigned kbh[8][2], kbl[8][2];
            #pragma unroll
            for (int p = 0; p < 4; ++p) {
                unsigned off = (unsigned)(((p * 16 + b_r) * 36 + kk * 8 + b_wo) * 4);
                ldsm4(kbh[2*p][0], kbh[2*p][1], kbh[2*p+1][0], kbh[2*p+1][1], aKh + off);
                ldsm4(kbl[2*p][0], kbl[2*p][1], kbl[2*p+1][0], kbl[2*p+1][1], aKl + off);
            }
            #pragma unroll
            for (int nt = 0; nt < 8; ++nt) {
                mma_bf16(sacc[nt], qfh[kk], kbh[nt], sacc[nt]);
                mma_bf16(sacc[nt], qfh[kk], kbl[nt], sacc[nt]);
                mma_bf16(sacc[nt], qfl[kk], kbh[nt], sacc[nt]);
            }
        }
        #pragma unroll
        for (int nt = 0; nt < 8; ++nt) {
            #pragma unroll
            for (int e = 0; e < 4; ++e) sacc[nt][e] *= 0.125f;
        }
        if (kt == qt) {
            #pragma unroll
            for (int nt = 0; nt < 8; ++nt) {
                int c = nt * 8 + 2 * t;
                if (c > r0)         sacc[nt][0] = -1e30f;
                if (c + 1 > r0)     sacc[nt][1] = -1e30f;
                if (c > r0 + 8)     sacc[nt][2] = -1e30f;
                if (c + 1 > r0 + 8) sacc[nt][3] = -1e30f;
            }
        }
        float tm0 = -1e30f, tm1 = -1e30f;
        #pragma unroll
        for (int nt = 0; nt < 8; ++nt) {
            tm0 = fmaxf(tm0, fmaxf(sacc[nt][0], sacc[nt][1]));
            tm1 = fmaxf(tm1, fmaxf(sacc[nt][2], sacc[nt][3]));
        }
        tm0 = fmaxf(tm0, __shfl_xor_sync(0xffffffffu, tm0, 1));
        tm0 = fmaxf(tm0, __shfl_xor_sync(0xffffffffu, tm0, 2));
        tm1 = fmaxf(tm1, __shfl_xor_sync(0xffffffffu, tm1, 1));
        tm1 = fmaxf(tm1, __shfl_xor_sync(0xffffffffu, tm1, 2));
        float mn0 = fmaxf(m0, tm0), mn1 = fmaxf(m1, tm1);
        float sc0 = __expf(m0 - mn0), sc1 = __expf(m1 - mn1);
        m0 = mn0; m1 = mn1;
        l0 *= sc0; l1 *= sc1;
        #pragma unroll
        for (int nt = 0; nt < 8; ++nt) {
            od[nt][0] *= sc0; od[nt][1] *= sc0;
            od[nt][2] *= sc1; od[nt][3] *= sc1;
        }
        #pragma unroll
        for (int nt = 0; nt < 8; ++nt) {
            sacc[nt][0] = __expf(sacc[nt][0] - m0);
            sacc[nt][1] = __expf(sacc[nt][1] - m0);
            sacc[nt][2] = __expf(sacc[nt][2] - m1);
            sacc[nt][3] = __expf(sacc[nt][3] - m1);
            l0 += sacc[nt][0] + sacc[nt][1];
            l1 += sacc[nt][2] + sacc[nt][3];
        }
        unsigned pah[4][4], pal[4][4];
        #pragma unroll
        for (int kk = 0; kk < 4; ++kk) {
            pack_split2(sacc[2*kk][0],   sacc[2*kk][1],   pah[kk][0], pal[kk][0]);
            pack_split2(sacc[2*kk][2],   sacc[2*kk][3],   pah[kk][1], pal[kk][1]);
            pack_split2(sacc[2*kk+1][0], sacc[2*kk+1][1], pah[kk][2], pal[kk][2]);
            pack_split2(sacc[2*kk+1][2], sacc[2*kk+1][3], pah[kk][3], pal[kk][3]);
        }
        #pragma unroll
        for (int kk = 0; kk < 4; ++kk) {
            unsigned vbh[8][2], vbl[8][2];
            #pragma unroll
            for (int p = 0; p < 4; ++p) {
                unsigned off = (unsigned)(((kk * 16 + v_r) * 36 + p * 8 + v_c) * 4);
                ldsm4t(vbh[2*p][0], vbh[2*p][1], vbh[2*p+1][0], vbh[2*p+1][1], aVh + off);
                ldsm4t(vbl[2*p][0], vbl[2*p][1], vbl[2*p+1][0], vbl[2*p+1][1], aVl + off);
            }
            #pragma unroll
            for (int nt = 0; nt < 8; ++nt) {
                mma_bf16(od[nt], pah[kk], vbh[nt], od[nt]);
                mma_bf16(od[nt], pah[kk], vbl[nt], od[nt]);
                mma_bf16(od[nt], pal[kk], vbh[nt], od[nt]);
            }
        }
        __syncthreads();
    }

    l0 += __shfl_xor_sync(0xffffffffu, l0, 1);
    l0 += __shfl_xor_sync(0xffffffffu, l0, 2);
    l1 += __shfl_xor_sync(0xffffffffu, l1, 1);
    l1 += __shfl_xor_sync(0xffffffffu, l1, 2);
    float i0 = 1.f / l0, i1 = 1.f / l1;
    int b = bh >> 4, h = bh & 15;
    long ob0 = ((long)(b * SD + qt * 64 + r0)) * DD + h * HDIM;
    long ob1 = ob0 + 8L * DD;
    #pragma unroll
    for (int nt = 0; nt < 8; ++nt) {
        int d = nt * 8 + 2 * t;
        __nv_bfloat16 hh, ll;
        split_bf(od[nt][0] * i0, hh, ll); oh_[ob0 + d] = hh;     ol_[ob0 + d] = ll;
        split_bf(od[nt][1] * i0, hh, ll); oh_[ob0 + d + 1] = hh; ol_[ob0 + d + 1] = ll;
        split_bf(od[nt][2] * i1, hh, ll); oh_[ob1 + d] = hh;     ol_[ob1 + d] = ll;
        split_bf(od[nt][3] * i1, hh, ll); oh_[ob1 + d + 1] = hh; ol_[ob1 + d + 1] = ll;
    }
}

// ---------------- SwiGLU vectorized -----------------------------------------
__global__ void k_silu(const float* __restrict__ g, const float* __restrict__ u,
                       __nv_bfloat16* __restrict__ oh, __nv_bfloat16* __restrict__ ol) {
    int idx = blockIdx.x * 256 + threadIdx.x;
    int row = idx / (MP / 4);
    int c4 = (idx - row * (MP / 4)) * 4;
    long base = (long)row * MP + c4;
    float4 gv = *(const float4*)(g + base);
    float4 uv = *(const float4*)(u + base);
    float v0 = (gv.x / (1.f + expf(-gv.x))) * uv.x;
    float v1 = (gv.y / (1.f + expf(-gv.y))) * uv.y;
    float v2 = (gv.z / (1.f + expf(-gv.z))) * uv.z;
    float v3 = (gv.w / (1.f + expf(-gv.w))) * uv.w;
    unsigned h0, l0, h1, l1;
    pack_split2(v0, v1, h0, l0);
    pack_split2(v2, v3, h1, l1);
    ((unsigned*)oh)[base >> 1] = h0;
    ((unsigned*)oh)[(base >> 1) + 1] = h1;
    ((unsigned*)ol)[base >> 1] = l0;
    ((unsigned*)ol)[(base >> 1) + 1] = l1;
}

// ---------------- head: both batch rows per block (W read once) -------------
__global__ void __launch_bounds__(256) k_head(const __nv_bfloat16* __restrict__ hh,
                                              const __nv_bfloat16* __restrict__ hl,
                                              const float* __restrict__ W,
                                              const float* __restrict__ bias,
                                              float* __restrict__ out) {
    int col = blockIdx.x * 256 + threadIdx.x;
    __shared__ float sx0[DD], sx1[DD];
    long r0 = (long)(SD - 1) * DD;
    long r1 = (long)(SD + SD - 1) * DD;
    for (int c = threadIdx.x; c < DD; c += 256) {
        sx0[c] = __bfloat162float(hh[r0 + c]) + __bfloat162float(hl[r0 + c]);
        sx1[c] = __bfloat162float(hh[r1 + c]) + __bfloat162float(hl[r1 + c]);
    }
    __syncthreads();
    if (col >= VV) return;
    float acc0 = 0.f, acc1 = 0.f;
    #pragma unroll 8
    for (int k = 0; k < DD; ++k) {
        float wv = W[(long)k * VV + col];
        acc0 += sx0[k] * wv;
        acc1 += sx1[k] * wv;
    }
    float bv = bias[col];
    out[col] = acc0 + bv;
    out[VV + col] = acc1 + bv;
}

// ---------------- driver -----------------------------------------------------
extern "C" void kernel_launch(void* const* d_in, const int* in_sizes, int n_in,
                              void* d_out, int out_size) {
    const int*   tokens = (const int*)  d_in[0];
    const float* embed  = (const float*)d_in[1];
    const float* Wqkv   = (const float*)d_in[2];
    const float* bqkv   = (const float*)d_in[3];
    const float* Wout   = (const float*)d_in[4];
    const float* bout   = (const float*)d_in[5];
    const float* ln1    = (const float*)d_in[6];
    const float* ln2    = (const float*)d_in[7];
    const float* Wg     = (const float*)d_in[8];
    const float* bg     = (const float*)d_in[9];
    const float* Wu     = (const float*)d_in[10];
    const float* bu     = (const float*)d_in[11];
    const float* Wd     = (const float*)d_in[12];
    const float* bd     = (const float*)d_in[13];
    const float* lnf    = (const float*)d_in[14];
    const float* Whead  = (const float*)d_in[15];
    const float* bhead  = (const float*)d_in[16];
    float* out = (float*)d_out;

    float *x, *gate, *up;
    __nv_bfloat16 *hh, *hl, *ath, *atl, *gth, *gtl;
    __nv_bfloat16 *qh, *ql, *kh, *kl, *vh, *vl;
    __nv_bfloat16 *wqkvh, *wqkvl, *wouth, *woutl, *wgh, *wgl, *wuh, *wul, *wdh, *wdl;
    cudaGetSymbolAddress((void**)&x,    g_x);
    cudaGetSymbolAddress((void**)&gate, g_gate);
    cudaGetSymbolAddress((void**)&up,   g_up);
    cudaGetSymbolAddress((void**)&hh,   g_h_h);
    cudaGetSymbolAddress((void**)&hl,   g_h_l);
    cudaGetSymbolAddress((void**)&ath,  g_attn_h);
    cudaGetSymbolAddress((void**)&atl,  g_attn_l);
    cudaGetSymbolAddress((void**)&gth,  g_gate_h);
    cudaGetSymbolAddress((void**)&gtl,  g_gate_l);
    cudaGetSymbolAddress((void**)&qh,   g_q_h);
    cudaGetSymbolAddress((void**)&ql,   g_q_l);
    cudaGetSymbolAddress((void**)&kh,   g_k_h);
    cudaGetSymbolAddress((void**)&kl,   g_k_l);
    cudaGetSymbolAddress((void**)&vh,   g_v_h);
    cudaGetSymbolAddress((void**)&vl,   g_v_l);
    cudaGetSymbolAddress((void**)&wqkvh, g_wqkvT_h);
    cudaGetSymbolAddress((void**)&wqkvl, g_wqkvT_l);
    cudaGetSymbolAddress((void**)&wouth, g_woutT_h);
    cudaGetSymbolAddress((void**)&woutl, g_woutT_l);
    cudaGetSymbolAddress((void**)&wgh,  g_wgT_h);
    cudaGetSymbolAddress((void**)&wgl,  g_wgT_l);
    cudaGetSymbolAddress((void**)&wuh,  g_wuT_h);
    cudaGetSymbolAddress((void**)&wul,  g_wuT_l);
    cudaGetSymbolAddress((void**)&wdh,  g_wdT_h);
    cudaGetSymbolAddress((void**)&wdl,  g_wdT_l);

    cudaFuncSetAttribute(k_gemm_bf3, cudaFuncAttributeMaxDynamicSharedMemorySize, 81920);
    cudaFuncSetAttribute(k_flash, cudaFuncAttributeMaxDynamicSharedMemorySize, 2 * FSTG * 4);
    const int GSM = 81920;
    const int FSM = 2 * FSTG * 4;
    const int PBLK = 296;
    float* p0 = gate;   // split-K partials reuse MLP fp32 scratch
    float* p1 = up;

    dim3 tb(32, 8);
    k_wsplit<<<dim3(96, 16, LL), tb>>>(Wqkv, wqkvh, wqkvl, DD, 3 * DD, DD,
                                       (long)DD * 3 * DD, (long)3 * DD * DD);
    k_wsplit<<<dim3(32, 16, LL), tb>>>(Wout, wouth, woutl, DD, DD, DD,
                                       (long)DD * DD, (long)DD * DD);
    k_wsplit<<<dim3(86, 16, LL), tb>>>(Wg, wgh, wgl, DD, MMF, DD,
                                       (long)DD * MMF, (long)MMF * DD);
    k_wsplit<<<dim3(86, 16, LL), tb>>>(Wu, wuh, wul, DD, MMF, DD,
                                       (long)DD * MMF, (long)MMF * DD);
    k_wsplit<<<dim3(32, 43, LL), tb>>>(Wd, wdh, wdl, MMF, DD, MP,
                                       (long)MMF * DD, (long)DD * MP);

    k_embed<<<NTOK, 256>>>(tokens, embed, x);
    k_rmsnorm<<<NTOK, 256>>>(x, ln1, hh, hl);

    for (int l = 0; l < LL; ++l) {
        // QKV with fused rope/split epilogue
        k_gemm_bf3<<<PBLK, 256, GSM>>>(hh, hl,
                                wqkvh + (long)l * 3 * DD * DD, wqkvl + (long)l * 3 * DD * DD,
                                bqkv + (long)l * 3 * DD, nullptr, nullptr,
                                nullptr, nullptr, nullptr, nullptr,
                                NTOK, DD, 3 * DD, 24, 3 * DD, 3 * DD, 1, 1,
                                qh, ql, kh, kl, vh, vl);

        k_flash<<<dim3(SD / 64, BH), 128, FSM>>>(qh, ql, kh, kl, vh, vl, ath, atl);

        // Wout split-K=2 -> p0,p1 (raw partials)
        k_gemm_bf3<<<256, 256, GSM>>>(ath, atl,
                                wouth + (long)l * DD * DD, woutl + (long)l * DD * DD,
                                nullptr, nullptr, p0,
                                nullptr, nullptr, nullptr, p1,
                                NTOK, DD, DD, 8, DD, DD, 0, 2,
                                nullptr, nullptr, nullptr, nullptr, nullptr, nullptr);
        k_comb_rms<<<NTOK, 256>>>(x, p0, p1, bout + (long)l * DD,
                                  ln2 + (long)l * DD, hh, hl);

        // Wg + Wu dual, MP-padded fp32 out
        k_gemm_bf3<<<PBLK, 256, GSM>>>(hh, hl,
                                wgh + (long)l * MMF * DD, wgl + (long)l * MMF * DD,
                                bg + (long)l * MMF, nullptr, gate,
                                wuh + (long)l * MMF * DD, wul + (long)l * MMF * DD,
                                bu + (long)l * MMF, up,
                                NTOK, DD, MMF, 22, MP, MP, 0, 1,
                                nullptr, nullptr, nullptr, nullptr, nullptr, nullptr);

        k_silu<<<NTOK * (MP / 4) / 256, 256>>>(gate, up, gth, gtl);

        // Wd split-K=2 -> p0,p1
        k_gemm_bf3<<<256, 256, GSM>>>(gth, gtl,
                                wdh + (long)l * DD * MP, wdl + (long)l * DD * MP,
                                nullptr, nullptr, p0,
                                nullptr, nullptr, nullptr, p1,
                                NTOK, MP, DD, 8, DD, DD, 0, 2,
                                nullptr, nullptr, nullptr, nullptr, nullptr, nullptr);
        const float* wnext = (l < LL - 1) ? (ln1 + (long)(l + 1) * DD) : lnf;
        k_comb_rms<<<NTOK, 256>>>(x, p0, p1, bd + (long)l * DD, wnext, hh, hl);
    }

    dim3 gh((VV + 255) / 256, 1);
    k_head<<<gh, 256>>>(hh, hl, Whead, bhead, out);
}

// round 15
// speedup vs baseline: 1.0841x; 1.0166x over previous
#include <cuda_runtime.h>
#include <cuda_bf16.h>
#include <math.h>

#define BD   2
#define SD   1024
#define DD   1024
#define HH   16
#define HDIM 64
#define LL   4
#define MMF  2730
#define MP   2752
#define VV   32000
#define NTOK (BD*SD)
#define BH   (BD*HH)

// ---------------- scratch (device globals; no allocation allowed) ----------
__device__ float g_x[NTOK*DD];
__device__ float g_gate[(long)NTOK*MP];     // also reused as split-K partial p0
__device__ float g_up[(long)NTOK*MP];       // also reused as split-K partial p1

__device__ __nv_bfloat16 g_h_h[NTOK*DD],    g_h_l[NTOK*DD];
__device__ __nv_bfloat16 g_attn_h[NTOK*DD], g_attn_l[NTOK*DD];
__device__ __nv_bfloat16 g_gate_h[NTOK*MP], g_gate_l[NTOK*MP];

__device__ __nv_bfloat16 g_q_h[BH*SD*HDIM], g_q_l[BH*SD*HDIM];
__device__ __nv_bfloat16 g_k_h[BH*SD*HDIM], g_k_l[BH*SD*HDIM];
__device__ __nv_bfloat16 g_v_h[BH*SD*HDIM], g_v_l[BH*SD*HDIM];

__device__ __nv_bfloat16 g_wqkvT_h[LL*3*DD*DD], g_wqkvT_l[LL*3*DD*DD];
__device__ __nv_bfloat16 g_woutT_h[LL*DD*DD],   g_woutT_l[LL*DD*DD];
__device__ __nv_bfloat16 g_wgT_h[LL*MMF*DD],    g_wgT_l[LL*MMF*DD];
__device__ __nv_bfloat16 g_wuT_h[LL*MMF*DD],    g_wuT_l[LL*MMF*DD];
__device__ __nv_bfloat16 g_wdT_h[(long)LL*DD*MP], g_wdT_l[(long)LL*DD*MP];

// ---------------- helpers ----------------------------------------------------
__device__ __forceinline__ void split_bf(float f, __nv_bfloat16& h, __nv_bfloat16& l) {
    h = __float2bfloat16(f);
    l = __float2bfloat16(f - __bfloat162float(h));
}
__device__ __forceinline__ void pack_split2(float a, float b, unsigned& hi, unsigned& lo) {
    __nv_bfloat162 th, tl;
    th.x = __float2bfloat16(a);
    th.y = __float2bfloat16(b);
    tl.x = __float2bfloat16(a - __bfloat162float(th.x));
    tl.y = __float2bfloat16(b - __bfloat162float(th.y));
    hi = *(unsigned*)&th;
    lo = *(unsigned*)&tl;
}
__device__ __forceinline__ void mma_bf16(float* d, const unsigned* a,
                                         const unsigned* b, const float* c) {
    asm volatile(
        "mma.sync.aligned.m16n8k16.row.col.f32.bf16.bf16.f32 "
        "{%0,%1,%2,%3}, {%4,%5,%6,%7}, {%8,%9}, {%10,%11,%12,%13};"
        : "=f"(d[0]), "=f"(d[1]), "=f"(d[2]), "=f"(d[3])
        : "r"(a[0]), "r"(a[1]), "r"(a[2]), "r"(a[3]),
          "r"(b[0]), "r"(b[1]),
          "f"(c[0]), "f"(c[1]), "f"(c[2]), "f"(c[3]));
}
__device__ __forceinline__ void ldsm4(unsigned& r0, unsigned& r1, unsigned& r2,
                                      unsigned& r3, unsigned addr) {
    asm volatile("ldmatrix.sync.aligned.m8n8.x4.shared.b16 {%0,%1,%2,%3}, [%4];"
                 : "=r"(r0), "=r"(r1), "=r"(r2), "=r"(r3) : "r"(addr));
}
__device__ __forceinline__ void ldsm4t(unsigned& r0, unsigned& r1, unsigned& r2,
                                       unsigned& r3, unsigned addr) {
    asm volatile("ldmatrix.sync.aligned.m8n8.x4.trans.shared.b16 {%0,%1,%2,%3}, [%4];"
                 : "=r"(r0), "=r"(r1), "=r"(r2), "=r"(r3) : "r"(addr));
}
__device__ __forceinline__ void cp16(unsigned saddr, const void* g) {
    asm volatile("cp.async.cg.shared.global [%0], [%1], 16;" :: "r"(saddr), "l"(g));
}
__device__ __forceinline__ void cp_commit() {
    asm volatile("cp.async.commit_group;");
}
template<int N> __device__ __forceinline__ void cp_wait() {
    asm volatile("cp.async.wait_group %0;" :: "n"(N));
}

// ---------------- weight transpose + bf16 split (16B stores) ----------------
// W: K x M fp32 -> Th/Tl: M x KP bf16 (k-major). Tile 64k x 32m, block (32,8).
__global__ void k_wsplit(const float* __restrict__ W,
                         __nv_bfloat16* __restrict__ Th,
                         __nv_bfloat16* __restrict__ Tl,
                         int K, int M, int KP, long wstride, long tstride) {
    W  += (long)blockIdx.z * wstride;
    Th += (long)blockIdx.z * tstride;
    Tl += (long)blockIdx.z * tstride;
    __shared__ float t[64][33];
    int m0 = blockIdx.x * 32, k0 = blockIdx.y * 64;
    int tx = threadIdx.x, ty = threadIdx.y;
    #pragma unroll
    for (int i = 0; i < 64; i += 8) {
        int k = k0 + ty + i, m = m0 + tx;
        t[ty + i][tx] = (k < K && m < M) ? W[(long)k * M + m] : 0.f;
    }
    __syncthreads();
    // store: each thread packs 8 consecutive k's for one m-row -> one 16B store per array
    int tid = ty * 32 + tx;
    int mi = tid >> 3, kg = tid & 7;
    int m = m0 + mi;
    if (m < M) {
        int kb = kg * 8;
        unsigned wh[4], wl[4];
        #pragma unroll
        for (int j = 0; j < 4; ++j) {
            __nv_bfloat16 h0, l0, h1, l1;
            split_bf(t[kb + 2 * j][mi], h0, l0);
            split_bf(t[kb + 2 * j + 1][mi], h1, l1);
            __nv_bfloat162 ph; ph.x = h0; ph.y = h1;
            __nv_bfloat162 pl; pl.x = l0; pl.y = l1;
            wh[j] = *(unsigned*)&ph;
            wl[j] = *(unsigned*)&pl;
        }
        long idx = (long)m * KP + k0 + kb;       // multiple of 8 -> 16B aligned
        *(uint4*)(Th + idx) = *(uint4*)wh;
        *(uint4*)(Tl + idx) = *(uint4*)wl;
    }
}

__global__ void k_embed(const int* __restrict__ tok, const float* __restrict__ emb,
                        float* __restrict__ x) {
    int i = blockIdx.x * 256 + threadIdx.x;
    int n = i >> 8, c4 = (i & 255) * 4;
    *(float4*)(x + (long)n * DD + c4) =
        *(const float4*)(emb + (long)tok[n] * DD + c4);
}

__global__ void __launch_bounds__(256) k_rmsnorm(const float* __restrict__ x,
                                                 const float* __restrict__ w,
                                                 __nv_bfloat16* __restrict__ oh,
                                                 __nv_bfloat16* __restrict__ ol) {
    int row = blockIdx.x;
    int c4 = threadIdx.x * 4;
    float4 xv = *(const float4*)(x + (long)row * DD + c4);
    float s = xv.x * xv.x + xv.y * xv.y + xv.z * xv.z + xv.w * xv.w;
    __shared__ float red[8];
    #pragma unroll
    for (int off = 16; off; off >>= 1) s += __shfl_xor_sync(0xffffffffu, s, off);
    if ((threadIdx.x & 31) == 0) red[threadIdx.x >> 5] = s;
    __syncthreads();
    if (threadIdx.x == 0) {
        float tt = 0.f;
        #pragma unroll
        for (int i = 0; i < 8; ++i) tt += red[i];
        red[0] = tt;
    }
    __syncthreads();
    float r = rsqrtf(red[0] * (1.0f / DD) + 1e-6f);
    float4 wv = *(const float4*)(w + c4);
    unsigned h0, l0, h1, l1;
    pack_split2(xv.x * r * wv.x, xv.y * r * wv.y, h0, l0);
    pack_split2(xv.z * r * wv.z, xv.w * r * wv.w, h1, l1);
    long wi = ((long)row * DD + c4) >> 1;
    ((unsigned*)oh)[wi] = h0;
    ((unsigned*)oh)[wi + 1] = h1;
    ((unsigned*)ol)[wi] = l0;
    ((unsigned*)ol)[wi + 1] = l1;
}

// ---- combine split-K partials + residual + bias, then rmsnorm -> bf16 split -
__global__ void __launch_bounds__(256) k_comb_rms(float* __restrict__ x,
                                                  const float* __restrict__ p0,
                                                  const float* __restrict__ p1,
                                                  const float* __restrict__ bias,
                                                  const float* __restrict__ w,
                                                  __nv_bfloat16* __restrict__ oh,
                                                  __nv_bfloat16* __restrict__ ol) {
    int row = blockIdx.x;
    int c4 = threadIdx.x * 4;
    long base = (long)row * DD + c4;
    float4 xv = *(float4*)(x + base);
    float4 a = *(const float4*)(p0 + base);
    float4 b = *(const float4*)(p1 + base);
    float4 bv = *(const float4*)(bias + c4);
    xv.x += a.x + b.x + bv.x;
    xv.y += a.y + b.y + bv.y;
    xv.z += a.z + b.z + bv.z;
    xv.w += a.w + b.w + bv.w;
    *(float4*)(x + base) = xv;
    float s = xv.x * xv.x + xv.y * xv.y + xv.z * xv.z + xv.w * xv.w;
    __shared__ float red[8];
    #pragma unroll
    for (int off = 16; off; off >>= 1) s += __shfl_xor_sync(0xffffffffu, s, off);
    if ((threadIdx.x & 31) == 0) red[threadIdx.x >> 5] = s;
    __syncthreads();
    if (threadIdx.x == 0) {
        float tt = 0.f;
        #pragma unroll
        for (int i = 0; i < 8; ++i) tt += red[i];
        red[0] = tt;
    }
    __syncthreads();
    float r = rsqrtf(red[0] * (1.0f / DD) + 1e-6f);
    float4 wv = *(const float4*)(w + c4);
    unsigned h0, l0, h1, l1;
    pack_split2(xv.x * r * wv.x, xv.y * r * wv.y, h0, l0);
    pack_split2(xv.z * r * wv.z, xv.w * r * wv.w, h1, l1);
    long wi = base >> 1;
    ((unsigned*)oh)[wi] = h0;
    ((unsigned*)oh)[wi + 1] = h1;
    ((unsigned*)ol)[wi] = l0;
    ((unsigned*)ol)[wi + 1] = l1;
}

// ---------------- bf16 split-3 GEMM: persistent + dual/splitK + qkv epilogue -
#define XS 20
#define ASZ (128*XS)
__global__ void __launch_bounds__(256, 2) k_gemm_bf3(
        const __nv_bfloat16* __restrict__ Ah_, const __nv_bfloat16* __restrict__ Al_,
        const __nv_bfloat16* __restrict__ B1h_, const __nv_bfloat16* __restrict__ B1l_,
        const float* __restrict__ bias1, const float* __restrict__ add,
        float* __restrict__ C1,
        const __nv_bfloat16* __restrict__ B2h_, const __nv_bfloat16* __restrict__ B2l_,
        const float* __restrict__ bias2, float* __restrict__ C2,
        int N, int K, int M, int tilesX, int ldC, int Mstore, int qkv_mode, int ksplit,
        __nv_bfloat16* qh, __nv_bfloat16* ql,
        __nv_bfloat16* kh, __nv_bfloat16* kl,
        __nv_bfloat16* vh, __nv_bfloat16* vl) {
    extern __shared__ unsigned sm[];
    const unsigned* Ahw = (const unsigned*)Ah_;
    const unsigned* Alw = (const unsigned*)Al_;
    int tid = threadIdx.x, wid = tid >> 5, lane = tid & 31;
    int wm = (wid & 1) * 64, wn = (wid >> 1) * 32;
    int Kw = K >> 1;
    int NC = Kw >> 4;
    int NCH = NC / ksplit;
    unsigned sbase = (unsigned)__cvta_generic_to_shared(sm);
    int tilesY = N >> 7;
    int per = tilesX * tilesY;
    int total = per * ((B2h_ || ksplit == 2) ? 2 : 1);

    int lrow0 = tid >> 2, lw4 = (tid & 3) * 4;
    int lrow1 = lrow0 + 64;
    int rq   = lane & 7;
    int a_r  = rq + ((lane >> 3) & 1) * 8;
    int a_wo = ((lane >> 4) << 2);
    int b_r  = rq + ((lane >> 4) << 3);
    int b_wo = (((lane >> 3) & 1) << 2);
    int g = lane >> 2, t = lane & 3;

    for (int tI = blockIdx.x; tI < total; tI += gridDim.x) {
        int sel = (tI >= per) ? 1 : 0;               // dual-B or K-half
        int tt = sel ? tI - per : tI;
        int by = tt / tilesX, bx = tt - by * tilesX;
        int br = by * 128, bc = bx * 128;
        const unsigned* Bhw = (const unsigned*)((B2h_ && sel) ? B2h_ : B1h_);
        const unsigned* Blw = (const unsigned*)((B2l_ && sel) ? B2l_ : B1l_);
        const float* bias = (B2h_ && sel) ? bias2 : bias1;
        float* C = sel ? C2 : C1;
        int c0 = (ksplit == 2 && sel) ? NCH : 0;

        int brow0 = bc + lrow0; if (brow0 >= M) brow0 = M - 1;
        int brow1 = bc + lrow1; if (brow1 >= M) brow1 = M - 1;
        float acc[4][4][4] = {};

        auto load_chunk = [&](int c, int stage) {
            int kw = c * 16 + lw4;
            unsigned sb = sbase + (unsigned)stage * (4u * ASZ * 4u);
            unsigned d0 = sb + (lrow0 * XS + lw4) * 4u;
            unsigned d1 = sb + (lrow1 * XS + lw4) * 4u;
            long a0 = (long)(br + lrow0) * Kw + kw;
            long a1 = (long)(br + lrow1) * Kw + kw;
            long b0 = (long)brow0 * Kw + kw;
            long b1 = (long)brow1 * Kw + kw;
            cp16(d0,                 Ahw + a0);
            cp16(d1,                 Ahw + a1);
            cp16(d0 + ASZ * 4u,      Alw + a0);
            cp16(d1 + ASZ * 4u,      Alw + a1);
            cp16(d0 + 2u * ASZ * 4u, Bhw + b0);
            cp16(d1 + 2u * ASZ * 4u, Bhw + b1);
            cp16(d0 + 3u * ASZ * 4u, Blw + b0);
            cp16(d1 + 3u * ASZ * 4u, Blw + b1);
            cp_commit();
        };

        load_chunk(c0, 0);

        for (int cl = 0; cl < NCH; ++cl) {
            if (cl + 1 < NCH) {
                load_chunk(c0 + cl + 1, (cl + 1) & 1);
                cp_wait<1>();
            } else {
                cp_wait<0>();
            }
            __syncthreads();
            unsigned stg = sbase + (unsigned)(cl & 1) * (4u * ASZ * 4u);
            unsigned aAh = stg;
            unsigned aAl = stg + ASZ * 4u;
            unsigned aBh = stg + 2u * ASZ * 4u;
            unsigned aBl = stg + 3u * ASZ * 4u;
            #pragma unroll
            for (int ks = 0; ks < 2; ++ks) {
                int kpb = ks * 8;
                unsigned ah[4][4], al[4][4], bh[4][2], bl[4][2];
                #pragma unroll
                for (int mt = 0; mt < 4; ++mt) {
                    unsigned off = (unsigned)(((wm + mt * 16 + a_r) * XS + kpb + a_wo) * 4);
                    ldsm4(ah[mt][0], ah[mt][1], ah[mt][2], ah[mt][3], aAh + off);
                    ldsm4(al[mt][0], al[mt][1], al[mt][2], al[mt][3], aAl + off);
                }
                #pragma unroll
                for (int p = 0; p < 2; ++p) {
                    unsigned off = (unsigned)(((wn + p * 16 + b_r) * XS + kpb + b_wo) * 4);
                    ldsm4(bh[2*p][0], bh[2*p][1], bh[2*p+1][0], bh[2*p+1][1], aBh + off);
                    ldsm4(bl[2*p][0], bl[2*p][1], bl[2*p+1][0], bl[2*p+1][1], aBl + off);
                }
                #pragma unroll
                for (int mt = 0; mt < 4; ++mt)
                    #pragma unroll
                    for (int nt = 0; nt < 4; ++nt) {
                        mma_bf16(acc[mt][nt], ah[mt], bh[nt], acc[mt][nt]);
                        mma_bf16(acc[mt][nt], ah[mt], bl[nt], acc[mt][nt]);
                        mma_bf16(acc[mt][nt], al[mt], bh[nt], acc[mt][nt]);
                    }
            }
            __syncthreads();
        }

        if (qkv_mode) {
            int sec = bc >> 10;
            #pragma unroll
            for (int nt = 0; nt < 4; ++nt) {
                int c0x = bc + wn + nt * 8 + 2 * t;
                int cc = c0x & 1023;
                int h = cc >> 6, j = (cc & 63) >> 1;
                float b0 = bias[c0x], b1 = bias[c0x + 1];
                float freq = exp2f(-0.41524101186f * (float)j);
                __nv_bfloat16* oh = (sec == 0) ? qh : (sec == 1) ? kh : vh;
                __nv_bfloat16* ol = (sec == 0) ? ql : (sec == 1) ? kl : vl;
                #pragma unroll
                for (int mt = 0; mt < 4; ++mt) {
                    #pragma unroll
                    for (int rr = 0; rr < 2; ++rr) {
                        int tok = br + wm + mt * 16 + g + rr * 8;
                        float e = acc[mt][nt][rr * 2 + 0] + b0;
                        float o = acc[mt][nt][rr * 2 + 1] + b1;
                        int s = tok & (SD - 1), b = tok >> 10;
                        if (sec < 2) {
                            float sn, cs;
                            sincosf((float)s * freq, &sn, &cs);
                            float e2 = e * cs - o * sn;
                            o = e * sn + o * cs;
                            e = e2;
                        }
                        long off = ((long)(b * HH + h) * SD + s) * 32 + j;
                        unsigned hi, lo;
                        pack_split2(e, o, hi, lo);
                        ((unsigned*)oh)[off] = hi;
                        ((unsigned*)ol)[off] = lo;
                    }
                }
            }
        } else {
            #pragma unroll
            for (int mt = 0; mt < 4; ++mt) {
                int r0 = br + wm + mt * 16 + g;
                #pragma unroll
                for (int nt = 0; nt < 4; ++nt) {
                    int c0x = bc + wn + nt * 8 + 2 * t;
                    const float* a4 = acc[mt][nt];
                    #pragma unroll
                    for (int e = 0; e < 2; ++e) {
                        int cx = c0x + e;
                        if (cx < Mstore) {
                            float v0, v1;
                            if (cx < M) {
                                float bv = bias ? bias[cx] : 0.f;
                                v0 = a4[e] + bv;
                                v1 = a4[2 + e] + bv;
                                if (add) {
                                    v0 += add[(long)r0 * ldC + cx];
                                    v1 += add[(long)(r0 + 8) * ldC + cx];
                                }
                            } else {
                                v0 = 0.f; v1 = 0.f;
                            }
                            C[(long)r0 * ldC + cx] = v0;
                            C[(long)(r0 + 8) * ldC + cx] = v1;
                        }
                    }
                }
            }
        }
        __syncthreads();
    }
}

// ---------------- flash attention (heavy-first across all bh) ---------------
#define FWPA 2304
#define FSTG (4*FWPA)
__global__ void __launch_bounds__(128) k_flash(
        const __nv_bfloat16* __restrict__ qh_, const __nv_bfloat16* __restrict__ ql_,
        const __nv_bfloat16* __restrict__ kh_, const __nv_bfloat16* __restrict__ kl_,
        const __nv_bfloat16* __restrict__ vh_, const __nv_bfloat16* __restrict__ vl_,
        __nv_bfloat16* __restrict__ oh_, __nv_bfloat16* __restrict__ ol_) {
    extern __shared__ unsigned fsm[];
    int bh = blockIdx.x;                           // bh fastest
    int qt = (int)gridDim.y - 1 - blockIdx.y;      // qt descending across waves
    int tid = threadIdx.x, wid = tid >> 5, lane = tid & 31;
    int g = lane >> 2, t = lane & 3;
    const unsigned* qhw = (const unsigned*)qh_;
    const unsigned* qlw = (const unsigned*)ql_;
    const unsigned* khw = (const unsigned*)kh_;
    const unsigned* klw = (const unsigned*)kl_;
    const unsigned* vhw = (const unsigned*)vh_;
    const unsigned* vlw = (const unsigned*)vl_;
    unsigned sb = (unsigned)__cvta_generic_to_shared(fsm);

    int rq  = lane & 7;
    int b_r = rq + ((lane >> 4) << 3);
    int b_wo = (((lane >> 3) & 1) << 2);
    int v_r = rq + ((lane >> 3) & 1) * 8;
    int v_c = (lane >> 4) << 2;

    long qbase = ((long)bh * SD + qt * 64) * 32;
    #pragma unroll
    for (int it = 0; it < 16; ++it) {
        int idx = tid + it * 128;
        int row = idx >> 5, col = idx & 31;
        fsm[row * 36 + col]        = qhw[qbase + row * 32 + col];
        fsm[FWPA + row * 36 + col] = qlw[qbase + row * 32 + col];
    }
    __syncthreads();
    int r0 = wid * 16 + g;
    unsigned qfh[4][4], qfl[4][4];
    #pragma unroll
    for (int kk = 0; kk < 4; ++kk) {
        qfh[kk][0] = fsm[r0 * 36 + kk * 8 + t];
        qfh[kk][1] = fsm[(r0 + 8) * 36 + kk * 8 + t];
        qfh[kk][2] = fsm[r0 * 36 + kk * 8 + t + 4];
        qfh[kk][3] = fsm[(r0 + 8) * 36 + kk * 8 + t + 4];
        qfl[kk][0] = fsm[FWPA + r0 * 36 + kk * 8 + t];
        qfl[kk][1] = fsm[FWPA + (r0 + 8) * 36 + kk * 8 + t];
        qfl[kk][2] = fsm[FWPA + r0 * 36 + kk * 8 + t + 4];
        qfl[kk][3] = fsm[FWPA + (r0 + 8) * 36 + kk * 8 + t + 4];
    }
    __syncthreads();

    auto loadKV = [&](int kt, int stg) {
        long kb = ((long)bh * SD + kt * 64) * 32;
        unsigned base = sb + (unsigned)stg * (FSTG * 4u);
        #pragma unroll
        for (int it = 0; it < 4; ++it) {
            int idx = tid + it * 128;
            int row = idx >> 3, wg = (idx & 7) * 4;
            unsigned d = base + (unsigned)(row * 36 + wg) * 4u;
            long gsrc = kb + row * 32 + wg;
            cp16(d,                   khw + gsrc);
            cp16(d + FWPA * 4u,       klw + gsrc);
            cp16(d + 2u * FWPA * 4u,  vhw + gsrc);
            cp16(d + 3u * FWPA * 4u,  vlw + gsrc);
        }
        cp_commit();
    };

    float m0 = -INFINITY, m1 = -INFINITY, l0 = 0.f, l1 = 0.f;
    float od[8][4] = {};

    loadKV(0, 0);
    for (int kt = 0; kt <= qt; ++kt) {
        if (kt + 1 <= qt) {
            loadKV(kt + 1, (kt + 1) & 1);
            cp_wait<1>();
        } else {
            cp_wait<0>();
        }
        __syncthreads();
        unsigned stg = sb + (unsigned)(kt & 1) * (FSTG * 4u);
        unsigned aKh = stg;
        unsigned aKl = stg + FWPA * 4u;
        unsigned aVh = stg + 2u * FWPA * 4u;
        unsigned aVl = stg + 3u * FWPA * 4u;

        float sacc[8][4] = {};
        #pragma unroll
        for (int kk = 0; kk < 4; ++kk) {
            unsigned kbh[8][2], kbl[8][2];
            #pragma unroll
            for (int p = 0; p < 4; ++p) {
                unsigned off = (unsigned)(((p * 16 + b_r) * 36 + kk * 8 + b_wo) * 4);
                ldsm4(kbh[2*p][0], kbh[2*p][1], kbh[2*p+1][0], kbh[2*p+1][1], aKh + off);
                ldsm4(kbl[2*p][0], kbl[2*p][1], kbl[2*p+1][0], kbl[2*p+1][1], aKl + off);
            }
            #pragma unroll
            for (int nt = 0; nt < 8; ++nt) {
                mma_bf16(sacc[nt], qfh[kk], kbh[nt], sacc[nt]);
                mma_bf16(sacc[nt], qfh[kk], kbl[nt], sacc[nt]);
                mma_bf16(sacc[nt], qfl[kk], kbh[nt], sacc[nt]);
            }
        }
        #pragma unroll
        for (int nt = 0; nt < 8; ++nt) {
            #pragma unroll
            for (int e = 0; e < 4; ++e) sacc[nt][e] *= 0.125f;
        }
        if (kt == qt) {
            #pragma unroll
            for (int nt = 0; nt < 8; ++nt) {
                int c = nt * 8 + 2 * t;
                if (c > r0)         sacc[nt][0] = -1e30f;
                if (c + 1 > r0)     sacc[nt][1] = -1e30f;
                if (c > r0 + 8)     sacc[nt][2] = -1e30f;
                if (c + 1 > r0 + 8) sacc[nt][3] = -1e30f;
            }
        }
        float tm0 = -1e30f, tm1 = -1e30f;
        #pragma unroll
        for (int nt = 0; nt < 8; ++nt) {
            tm0 = fmaxf(tm0, fmaxf(sacc[nt][0], sacc[nt][1]));
            tm1 = fmaxf(tm1, fmaxf(sacc[nt][2], sacc[nt][3]));
        }
        tm0 = fmaxf(tm0, __shfl_xor_sync(0xffffffffu, tm0, 1));
        tm0 = fmaxf(tm0, __shfl_xor_sync(0xffffffffu, tm0, 2));
        tm1 = fmaxf(tm1, __shfl_xor_sync(0xffffffffu, tm1, 1));
        tm1 = fmaxf(tm1, __shfl_xor_sync(0xffffffffu, tm1, 2));
        float mn0 = fmaxf(m0, tm0), mn1 = fmaxf(m1, tm1);
        float sc0 = __expf(m0 - mn0), sc1 = __expf(m1 - mn1);
        m0 = mn0; m1 = mn1;
        l0 *= sc0; l1 *= sc1;
        #pragma unroll
        for (int nt = 0; nt < 8; ++nt) {
            od[nt][0] *= sc0; od[nt][1] *= sc0;
            od[nt][2] *= sc1; od[nt][3] *= sc1;
        }
        #pragma unroll
        for (int nt = 0; nt < 8; ++nt) {
            sacc[nt][0] = __expf(sacc[nt][0] - m0);
            sacc[nt][1] = __expf(sacc[nt][1] - m0);
            sacc[nt][2] = __expf(sacc[nt][2] - m1);
            sacc[nt][3] = __expf(sacc[nt][3] - m1);
            l0 += sacc[nt][0] + sacc[nt][1];
            l1 += sacc[nt][2] + sacc[nt][3];
        }
        unsigned pah[4][4], pal[4][4];
        #pragma unroll
        for (int kk = 0; kk < 4; ++kk) {
            pack_split2(sacc[2*kk][0],   sacc[2*kk][1],   pah[kk][0], pal[kk][0]);
            pack_split2(sacc[2*kk][2],   sacc[2*kk][3],   pah[kk][1], pal[kk][1]);
            pack_split2(sacc[2*kk+1][0], sacc[2*kk+1][1], pah[kk][2], pal[kk][2]);
            pack_split2(sacc[2*kk+1][2], sacc[2*kk+1][3], pah[kk][3], pal[kk][3]);
        }
        #pragma unroll
        for (int kk = 0; kk < 4; ++kk) {
            unsigned vbh[8][2], vbl[8][2];
            #pragma unroll
            for (int p = 0; p < 4; ++p) {
                unsigned off = (unsigned)(((kk * 16 + v_r) * 36 + p * 8 + v_c) * 4);
                ldsm4t(vbh[2*p][0], vbh[2*p][1], vbh[2*p+1][0], vbh[2*p+1][1], aVh + off);
                ldsm4t(vbl[2*p][0], vbl[2*p][1], vbl[2*p+1][0], vbl[2*p+1][1], aVl + off);
            }
            #pragma unroll
            for (int nt = 0; nt < 8; ++nt) {
                mma_bf16(od[nt], pah[kk], vbh[nt], od[nt]);
                mma_bf16(od[nt], pah[kk], vbl[nt], od[nt]);
                mma_bf16(od[nt], pal[kk], vbh[nt], od[nt]);
            }
        }
        __syncthreads();
    }

    l0 += __shfl_xor_sync(0xffffffffu, l0, 1);
    l0 += __shfl_xor_sync(0xffffffffu, l0, 2);
    l1 += __shfl_xor_sync(0xffffffffu, l1, 1);
    l1 += __shfl_xor_sync(0xffffffffu, l1, 2);
    float i0 = 1.f / l0, i1 = 1.f / l1;
    int b = bh >> 4, h = bh & 15;
    long ob0 = ((long)(b * SD + qt * 64 + r0)) * DD + h * HDIM;
    long ob1 = ob0 + 8L * DD;
    #pragma unroll
    for (int nt = 0; nt < 8; ++nt) {
        int d = nt * 8 + 2 * t;
        __nv_bfloat16 hh, ll;
        split_bf(od[nt][0] * i0, hh, ll); oh_[ob0 + d] = hh;     ol_[ob0 + d] = ll;
        split_bf(od[nt][1] * i0, hh, ll); oh_[ob0 + d + 1] = hh; ol_[ob0 + d + 1] = ll;
        split_bf(od[nt][2] * i1, hh, ll); oh_[ob1 + d] = hh;     ol_[ob1 + d] = ll;
        split_bf(od[nt][3] * i1, hh, ll); oh_[ob1 + d + 1] = hh; ol_[ob1 + d + 1] = ll;
    }
}

// ---------------- SwiGLU vectorized -----------------------------------------
__global__ void k_silu(const float* __restrict__ g, const float* __restrict__ u,
                       __nv_bfloat16* __restrict__ oh, __nv_bfloat16* __restrict__ ol) {
    int idx = blockIdx.x * 256 + threadIdx.x;
    int row = idx / (MP / 4);
    int c4 = (idx - row * (MP / 4)) * 4;
    long base = (long)row * MP + c4;
    float4 gv = *(const float4*)(g + base);
    float4 uv = *(const float4*)(u + base);
    float v0 = (gv.x / (1.f + expf(-gv.x))) * uv.x;
    float v1 = (gv.y / (1.f + expf(-gv.y))) * uv.y;
    float v2 = (gv.z / (1.f + expf(-gv.z))) * uv.z;
    float v3 = (gv.w / (1.f + expf(-gv.w))) * uv.w;
    unsigned h0, l0, h1, l1;
    pack_split2(v0, v1, h0, l0);
    pack_split2(v2, v3, h1, l1);
    ((unsigned*)oh)[base >> 1] = h0;
    ((unsigned*)oh)[(base >> 1) + 1] = h1;
    ((unsigned*)ol)[base >> 1] = l0;
    ((unsigned*)ol)[(base >> 1) + 1] = l1;
}

// ---------------- head: both batch rows per block (W read once) -------------
__global__ void __launch_bounds__(256) k_head(const __nv_bfloat16* __restrict__ hh,
                                              const __nv_bfloat16* __restrict__ hl,
                                              const float* __restrict__ W,
                                              const float* __restrict__ bias,
                                              float* __restrict__ out) {
    int col = blockIdx.x * 256 + threadIdx.x;
    __shared__ float sx0[DD], sx1[DD];
    long r0 = (long)(SD - 1) * DD;
    long r1 = (long)(SD + SD - 1) * DD;
    for (int c = threadIdx.x; c < DD; c += 256) {
        sx0[c] = __bfloat162float(hh[r0 + c]) + __bfloat162float(hl[r0 + c]);
        sx1[c] = __bfloat162float(hh[r1 + c]) + __bfloat162float(hl[r1 + c]);
    }
    __syncthreads();
    if (col >= VV) return;
    float acc0 = 0.f, acc1 = 0.f;
    #pragma unroll 8
    for (int k = 0; k < DD; ++k) {
        float wv = W[(long)k * VV + col];
        acc0 += sx0[k] * wv;
        acc1 += sx1[k] * wv;
    }
    float bv = bias[col];
    out[col] = acc0 + bv;
    out[VV + col] = acc1 + bv;
}

// ---------------- driver -----------------------------------------------------
extern "C" void kernel_launch(void* const* d_in, const int* in_sizes, int n_in,
                              void* d_out, int out_size) {
    const int*   tokens = (const int*)  d_in[0];
    const float* embed  = (const float*)d_in[1];
    const float* Wqkv   = (const float*)d_in[2];
    const float* bqkv   = (const float*)d_in[3];
    const float* Wout   = (const float*)d_in[4];
    const float* bout   = (const float*)d_in[5];
    const float* ln1    = (const float*)d_in[6];
    const float* ln2    = (const float*)d_in[7];
    const float* Wg     = (const float*)d_in[8];
    const float* bg     = (const float*)d_in[9];
    const float* Wu     = (const float*)d_in[10];
    const float* bu     = (const float*)d_in[11];
    const float* Wd     = (const float*)d_in[12];
    const float* bd     = (const float*)d_in[13];
    const float* lnf    = (const float*)d_in[14];
    const float* Whead  = (const float*)d_in[15];
    const float* bhead  = (const float*)d_in[16];
    float* out = (float*)d_out;

    float *x, *gate, *up;
    __nv_bfloat16 *hh, *hl, *ath, *atl, *gth, *gtl;
    __nv_bfloat16 *qh, *ql, *kh, *kl, *vh, *vl;
    __nv_bfloat16 *wqkvh, *wqkvl, *wouth, *woutl, *wgh, *wgl, *wuh, *wul, *wdh, *wdl;
    cudaGetSymbolAddress((void**)&x,    g_x);
    cudaGetSymbolAddress((void**)&gate, g_gate);
    cudaGetSymbolAddress((void**)&up,   g_up);
    cudaGetSymbolAddress((void**)&hh,   g_h_h);
    cudaGetSymbolAddress((void**)&hl,   g_h_l);
    cudaGetSymbolAddress((void**)&ath,  g_attn_h);
    cudaGetSymbolAddress((void**)&atl,  g_attn_l);
    cudaGetSymbolAddress((void**)&gth,  g_gate_h);
    cudaGetSymbolAddress((void**)&gtl,  g_gate_l);
    cudaGetSymbolAddress((void**)&qh,   g_q_h);
    cudaGetSymbolAddress((void**)&ql,   g_q_l);
    cudaGetSymbolAddress((void**)&kh,   g_k_h);
    cudaGetSymbolAddress((void**)&kl,   g_k_l);
    cudaGetSymbolAddress((void**)&vh,   g_v_h);
    cudaGetSymbolAddress((void**)&vl,   g_v_l);
    cudaGetSymbolAddress((void**)&wqkvh, g_wqkvT_h);
    cudaGetSymbolAddress((void**)&wqkvl, g_wqkvT_l);
    cudaGetSymbolAddress((void**)&wouth, g_woutT_h);
    cudaGetSymbolAddress((void**)&woutl, g_woutT_l);
    cudaGetSymbolAddress((void**)&wgh,  g_wgT_h);
    cudaGetSymbolAddress((void**)&wgl,  g_wgT_l);
    cudaGetSymbolAddress((void**)&wuh,  g_wuT_h);
    cudaGetSymbolAddress((void**)&wul,  g_wuT_l);
    cudaGetSymbolAddress((void**)&wdh,  g_wdT_h);
    cudaGetSymbolAddress((void**)&wdl,  g_wdT_l);

    cudaFuncSetAttribute(k_gemm_bf3, cudaFuncAttributeMaxDynamicSharedMemorySize, 81920);
    cudaFuncSetAttribute(k_flash, cudaFuncAttributeMaxDynamicSharedMemorySize, 2 * FSTG * 4);
    const int GSM = 81920;
    const int FSM = 2 * FSTG * 4;
    const int PBLK = 296;
    float* p0 = gate;   // split-K partials reuse MLP fp32 scratch
    float* p1 = up;

    dim3 tb(32, 8);
    k_wsplit<<<dim3(96, 16, LL), tb>>>(Wqkv, wqkvh, wqkvl, DD, 3 * DD, DD,
                                       (long)DD * 3 * DD, (long)3 * DD * DD);
    k_wsplit<<<dim3(32, 16, LL), tb>>>(Wout, wouth, woutl, DD, DD, DD,
                                       (long)DD * DD, (long)DD * DD);
    k_wsplit<<<dim3(86, 16, LL), tb>>>(Wg, wgh, wgl, DD, MMF, DD,
                                       (long)DD * MMF, (long)MMF * DD);
    k_wsplit<<<dim3(86, 16, LL), tb>>>(Wu, wuh, wul, DD, MMF, DD,
                                       (long)DD * MMF, (long)MMF * DD);
    k_wsplit<<<dim3(32, 43, LL), tb>>>(Wd, wdh, wdl, MMF, DD, MP,
                                       (long)MMF * DD, (long)DD * MP);

    k_embed<<<NTOK, 256>>>(tokens, embed, x);
    k_rmsnorm<<<NTOK, 256>>>(x, ln1, hh, hl);

    for (int l = 0; l < LL; ++l) {
        // QKV with fused rope/split epilogue
        k_gemm_bf3<<<PBLK, 256, GSM>>>(hh, hl,
                                wqkvh + (long)l * 3 * DD * DD, wqkvl + (long)l * 3 * DD * DD,
                                bqkv + (long)l * 3 * DD, nullptr, nullptr,
                                nullptr, nullptr, nullptr, nullptr,
                                NTOK, DD, 3 * DD, 24, 3 * DD, 3 * DD, 1, 1,
                                qh, ql, kh, kl, vh, vl);

        k_flash<<<dim3(BH, SD / 64), 128, FSM>>>(qh, ql, kh, kl, vh, vl, ath, atl);

        // Wout split-K=2 -> p0,p1 (raw partials)
        k_gemm_bf3<<<256, 256, GSM>>>(ath, atl,
                                wouth + (long)l * DD * DD, woutl + (long)l * DD * DD,
                                nullptr, nullptr, p0,
                                nullptr, nullptr, nullptr, p1,
                                NTOK, DD, DD, 8, DD, DD, 0, 2,
                                nullptr, nullptr, nullptr, nullptr, nullptr, nullptr);
        k_comb_rms<<<NTOK, 256>>>(x, p0, p1, bout + (long)l * DD,
                                  ln2 + (long)l * DD, hh, hl);

        // Wg + Wu dual, MP-padded fp32 out
        k_gemm_bf3<<<PBLK, 256, GSM>>>(hh, hl,
                                wgh + (long)l * MMF * DD, wgl + (long)l * MMF * DD,
                                bg + (long)l * MMF, nullptr, gate,
                                wuh + (long)l * MMF * DD, wul + (long)l * MMF * DD,
                                bu + (long)l * MMF, up,
                                NTOK, DD, MMF, 22, MP, MP, 0, 1,
                                nullptr, nullptr, nullptr, nullptr, nullptr, nullptr);

        k_silu<<<NTOK * (MP / 4) / 256, 256>>>(gate, up, gth, gtl);

        // Wd split-K=2 -> p0,p1
        k_gemm_bf3<<<256, 256, GSM>>>(gth, gtl,
                                wdh + (long)l * DD * MP, wdl + (long)l * DD * MP,
                                nullptr, nullptr, p0,
                                nullptr, nullptr, nullptr, p1,
                                NTOK, MP, DD, 8, DD, DD, 0, 2,
                                nullptr, nullptr, nullptr, nullptr, nullptr, nullptr);
        const float* wnext = (l < LL - 1) ? (ln1 + (long)(l + 1) * DD) : lnf;
        k_comb_rms<<<NTOK, 256>>>(x, p0, p1, bd + (long)l * DD, wnext, hh, hl);
    }

    dim3 gh((VV + 255) / 256, 1);
    k_head<<<gh, 256>>>(hh, hl, Whead, bhead, out);
}